// round 4
// baseline (speedup 1.0000x reference)
#include <cuda_runtime.h>
#include <cuda_bf16.h>
#include <math.h>

#define NN 100000
#define EE 800000
#define HIDC 128

// ---------------- scratch (device globals; no allocations allowed) ----------
__device__ float g_h_d[NN * HIDC];
__device__ float g_h_p[NN * HIDC];
__device__ float g_Fd_dp[NN * HIDC];
__device__ float g_Fp_dp[NN * HIDC];
__device__ float g_Fp_pd[NN * HIDC];
__device__ float g_Fd_pd[NN * HIDC];
__device__ float g_agg_d[NN * HIDC];
__device__ float g_agg_p[NN * HIDC];

__device__ float g_el_d_dp[NN * 4];
__device__ float g_er_p_dp[NN * 4];
__device__ float g_el_p_pd[NN * 4];
__device__ float g_er_d_pd[NN * 4];

__device__ int g_deg_dp[NN];
__device__ int g_deg_pd[NN];
__device__ int g_cur_dp[NN];
__device__ int g_cur_pd[NN];
__device__ int g_off_dp[NN];
__device__ int g_off_pd[NN];
__device__ int g_bsum[512];
__device__ int g_bscan[512];
__device__ int g_ssrc_dp[EE];
__device__ int g_ssrc_pd[EE];

// ---------------- GEMM: C[M,128] = A[M,128] @ W[128,128] (+bias)(+relu) -----
// BM=64, BN=128(full), 256 threads, thread-tile 8 rows x 4 cols (cols strided
// by 32 for coalesced C stores). K chunked by 32; A tile transposed with +65
// padding (conflict-free stores, broadcast loads), W chunk contiguous float4.
template <bool RELU>
__global__ __launch_bounds__(256) void gemm128_kernel(
    const float* __restrict__ A, const float* __restrict__ W,
    const float* __restrict__ bias, float* __restrict__ C, int M) {
  __shared__ float As[32 * 65];    // As[kk*65 + r]
  __shared__ float Ws[32 * 128];   // Ws[kk*128 + c]
  const int tid = threadIdx.x;
  const int tr = tid >> 5;         // 0..7  (row group)
  const int tc = tid & 31;         // 0..31 (col lane)
  const int row0 = blockIdx.x * 64;

  float acc[8][4];
#pragma unroll
  for (int i = 0; i < 8; i++)
#pragma unroll
    for (int j = 0; j < 4; j++) acc[i][j] = 0.f;

  for (int kc = 0; kc < 128; kc += 32) {
    // A chunk: 64 rows x 32 k, coalesced gmem, transposed smem store
#pragma unroll
    for (int t = 0; t < 8; t++) {
      int idx = t * 256 + tid;        // 0..2047
      int r = idx >> 5, kk = idx & 31;
      int row = row0 + r;
      float v = (row < M) ? A[row * 128 + kc + kk] : 0.f;
      As[kk * 65 + r] = v;
    }
    // W chunk: rows [kc,kc+32) are 4096 contiguous floats
    {
      const float4* Wg = reinterpret_cast<const float4*>(W + kc * 128);
      float4* Wsv = reinterpret_cast<float4*>(Ws);
#pragma unroll
      for (int t = 0; t < 4; t++) {
        int idx = t * 256 + tid;      // 0..1023 float4s
        Wsv[idx] = Wg[idx];
      }
    }
    __syncthreads();

#pragma unroll 4
    for (int kk = 0; kk < 32; kk++) {
      float a[8], b[4];
#pragma unroll
      for (int i = 0; i < 8; i++) a[i] = As[kk * 65 + tr * 8 + i];
#pragma unroll
      for (int j = 0; j < 4; j++) b[j] = Ws[kk * 128 + tc + 32 * j];
#pragma unroll
      for (int i = 0; i < 8; i++)
#pragma unroll
        for (int j = 0; j < 4; j++) acc[i][j] = fmaf(a[i], b[j], acc[i][j]);
    }
    __syncthreads();
  }

#pragma unroll
  for (int i = 0; i < 8; i++) {
    int row = row0 + tr * 8 + i;
    if (row >= M) continue;
#pragma unroll
    for (int j = 0; j < 4; j++) {
      int c = tc + 32 * j;
      float v = acc[i][j];
      if (bias) v += bias[c];
      if (RELU) v = fmaxf(v, 0.f);
      C[row * 128 + c] = v;
    }
  }
}

// ---------------- attention score: out[n][h] = sum_d F[n,h,d]*avec[h,d] -----
__global__ void attn_score_kernel(const float* __restrict__ F,
                                  const float* __restrict__ avec,
                                  float* __restrict__ out, int n) {
  int w = (blockIdx.x * blockDim.x + threadIdx.x) >> 5;
  int lane = threadIdx.x & 31;
  if (w >= n) return;
  const float* fr = F + w * 128;
#pragma unroll
  for (int h = 0; h < 4; h++) {
    float v = fr[h * 32 + lane] * avec[h * 32 + lane];
#pragma unroll
    for (int o = 16; o; o >>= 1) v += __shfl_xor_sync(0xffffffffu, v, o);
    if (lane == 0) out[w * 4 + h] = v;
  }
}

// ---------------- CSR build ------------------------------------------------
__global__ void zero4_kernel(int* a, int* b, int* c, int* d, int n) {
  int i = blockIdx.x * blockDim.x + threadIdx.x;
  if (i < n) { a[i] = 0; b[i] = 0; c[i] = 0; d[i] = 0; }
}

__global__ void degree_kernel(const int* __restrict__ dst, int* __restrict__ deg,
                              int n) {
  int i = blockIdx.x * blockDim.x + threadIdx.x;
  if (i < n) atomicAdd(&deg[dst[i]], 1);
}

__global__ void scan_block_kernel(const int* __restrict__ in,
                                  int* __restrict__ outExcl,
                                  int* __restrict__ bsums, int n) {
  __shared__ int s[512];
  int tid = threadIdx.x;
  int i = blockIdx.x * 512 + tid;
  int v = (i < n) ? in[i] : 0;
  s[tid] = v;
  __syncthreads();
  for (int off = 1; off < 512; off <<= 1) {
    int t = (tid >= off) ? s[tid - off] : 0;
    __syncthreads();
    s[tid] += t;
    __syncthreads();
  }
  if (i < n) outExcl[i] = s[tid] - v;
  if (tid == 511 && bsums) bsums[blockIdx.x] = s[511];
}

__global__ void scan_add_kernel(int* __restrict__ outExcl,
                                const int* __restrict__ bscan, int n) {
  int i = blockIdx.x * 512 + threadIdx.x;
  if (i < n) outExcl[i] += bscan[blockIdx.x];
}

__global__ void scatter_kernel(const int* __restrict__ src,
                               const int* __restrict__ dst,
                               const int* __restrict__ off, int* __restrict__ cur,
                               int* __restrict__ ssrc, int n) {
  int i = blockIdx.x * blockDim.x + threadIdx.x;
  if (i < n) {
    int d = dst[i];
    int p = atomicAdd(&cur[d], 1);
    ssrc[off[d] + p] = src[i];
  }
}

// ---------------- GAT aggregation: one warp per dst node -------------------
// online softmax (single gather pass), then coalesced message accumulation.
__global__ void gat_agg_kernel(const int* __restrict__ off,
                               const int* __restrict__ ssrc,
                               const float* __restrict__ el,
                               const float* __restrict__ er,
                               const float* __restrict__ Fsrc,
                               const float* __restrict__ bias,
                               float* __restrict__ out, int n, int etot) {
  int w = (blockIdx.x * blockDim.x + threadIdx.x) >> 5;
  int lane = threadIdx.x & 31;
  if (w >= n) return;

  int beg = off[w];
  int end = (w + 1 < n) ? off[w + 1] : etot;

  const float4* elv = reinterpret_cast<const float4*>(el);
  float4 erv = reinterpret_cast<const float4*>(er)[w];

  const float NEG = -1e30f;
  float m0 = NEG, m1 = NEG, m2 = NEG, m3 = NEG;
  float s0 = 0.f, s1 = 0.f, s2 = 0.f, s3 = 0.f;

  // pass 1: per-lane online softmax stats over strided edges
  for (int i = beg + lane; i < end; i += 32) {
    int sp = ssrc[i];
    float4 v = elv[sp];
    float e0 = v.x + erv.x; e0 = (e0 > 0.f) ? e0 : 0.2f * e0;
    float e1 = v.y + erv.y; e1 = (e1 > 0.f) ? e1 : 0.2f * e1;
    float e2 = v.z + erv.z; e2 = (e2 > 0.f) ? e2 : 0.2f * e2;
    float e3 = v.w + erv.w; e3 = (e3 > 0.f) ? e3 : 0.2f * e3;
    float nm;
    nm = fmaxf(m0, e0); s0 = s0 * __expf(m0 - nm) + __expf(e0 - nm); m0 = nm;
    nm = fmaxf(m1, e1); s1 = s1 * __expf(m1 - nm) + __expf(e1 - nm); m1 = nm;
    nm = fmaxf(m2, e2); s2 = s2 * __expf(m2 - nm) + __expf(e2 - nm); m2 = nm;
    nm = fmaxf(m3, e3); s3 = s3 * __expf(m3 - nm) + __expf(e3 - nm); m3 = nm;
  }
  // warp combine: global max then rescaled sum
  float M0 = m0, M1 = m1, M2 = m2, M3 = m3;
#pragma unroll
  for (int o = 16; o; o >>= 1) {
    M0 = fmaxf(M0, __shfl_xor_sync(0xffffffffu, M0, o));
    M1 = fmaxf(M1, __shfl_xor_sync(0xffffffffu, M1, o));
    M2 = fmaxf(M2, __shfl_xor_sync(0xffffffffu, M2, o));
    M3 = fmaxf(M3, __shfl_xor_sync(0xffffffffu, M3, o));
  }
  float t0 = s0 * __expf(m0 - M0);
  float t1 = s1 * __expf(m1 - M1);
  float t2 = s2 * __expf(m2 - M2);
  float t3 = s3 * __expf(m3 - M3);
#pragma unroll
  for (int o = 16; o; o >>= 1) {
    t0 += __shfl_xor_sync(0xffffffffu, t0, o);
    t1 += __shfl_xor_sync(0xffffffffu, t1, o);
    t2 += __shfl_xor_sync(0xffffffffu, t2, o);
    t3 += __shfl_xor_sync(0xffffffffu, t3, o);
  }
  float r0 = 1.0f / t0, r1 = 1.0f / t1, r2 = 1.0f / t2, r3 = 1.0f / t3;

  // pass 2: whole warp per edge, coalesced 128B loads per head
  float a0 = 0.f, a1 = 0.f, a2 = 0.f, a3 = 0.f;
  for (int i = beg; i < end; i++) {
    int sp = ssrc[i];                 // same addr all lanes -> broadcast
    float4 v = elv[sp];
    float e0 = v.x + erv.x; e0 = (e0 > 0.f) ? e0 : 0.2f * e0;
    float e1 = v.y + erv.y; e1 = (e1 > 0.f) ? e1 : 0.2f * e1;
    float e2 = v.z + erv.z; e2 = (e2 > 0.f) ? e2 : 0.2f * e2;
    float e3 = v.w + erv.w; e3 = (e3 > 0.f) ? e3 : 0.2f * e3;
    float c0 = __expf(e0 - M0) * r0;
    float c1 = __expf(e1 - M1) * r1;
    float c2 = __expf(e2 - M2) * r2;
    float c3 = __expf(e3 - M3) * r3;
    const float* fr = Fsrc + sp * 128;
    a0 = fmaf(c0, fr[lane],      a0);
    a1 = fmaf(c1, fr[32 + lane], a1);
    a2 = fmaf(c2, fr[64 + lane], a2);
    a3 = fmaf(c3, fr[96 + lane], a3);
  }
  float* o = out + w * 128;
  o[lane]      = a0 + bias[lane];
  o[32 + lane] = a1 + bias[32 + lane];
  o[64 + lane] = a2 + bias[64 + lane];
  o[96 + lane] = a3 + bias[96 + lane];
}

// ---------------- launch ---------------------------------------------------
static inline void* sym(const void* s) {
  void* p = nullptr;
  cudaGetSymbolAddress(&p, s);
  return p;
}

extern "C" void kernel_launch(void* const* d_in, const int* in_sizes, int n_in,
                              void* d_out, int out_size) {
  const float* x_drug = (const float*)d_in[0];
  const float* x_prot = (const float*)d_in[1];
  const int* src_dp = (const int*)d_in[2];
  const int* dst_dp = (const int*)d_in[3];
  const int* src_pd = (const int*)d_in[4];
  const int* dst_pd = (const int*)d_in[5];
  const float* W_in_d = (const float*)d_in[6];
  const float* b_in_d = (const float*)d_in[7];
  const float* W_in_p = (const float*)d_in[8];
  const float* b_in_p = (const float*)d_in[9];
  const float* W_dp   = (const float*)d_in[10];
  const float* al_dp  = (const float*)d_in[11];
  const float* ar_dp  = (const float*)d_in[12];
  const float* bias_dp= (const float*)d_in[13];
  const float* W_pd   = (const float*)d_in[14];
  const float* al_pd  = (const float*)d_in[15];
  const float* ar_pd  = (const float*)d_in[16];
  const float* bias_pd= (const float*)d_in[17];
  const float* W_out_d= (const float*)d_in[18];
  const float* b_out_d= (const float*)d_in[19];
  const float* W_out_p= (const float*)d_in[20];
  const float* b_out_p= (const float*)d_in[21];
  float* out = (float*)d_out;

  float* h_d  = (float*)sym(g_h_d);
  float* h_p  = (float*)sym(g_h_p);
  float* Fd_dp= (float*)sym(g_Fd_dp);
  float* Fp_dp= (float*)sym(g_Fp_dp);
  float* Fp_pd= (float*)sym(g_Fp_pd);
  float* Fd_pd= (float*)sym(g_Fd_pd);
  float* agg_d= (float*)sym(g_agg_d);
  float* agg_p= (float*)sym(g_agg_p);
  float* el_d_dp = (float*)sym(g_el_d_dp);
  float* er_p_dp = (float*)sym(g_er_p_dp);
  float* el_p_pd = (float*)sym(g_el_p_pd);
  float* er_d_pd = (float*)sym(g_er_d_pd);
  int* deg_dp = (int*)sym(g_deg_dp);
  int* deg_pd = (int*)sym(g_deg_pd);
  int* cur_dp = (int*)sym(g_cur_dp);
  int* cur_pd = (int*)sym(g_cur_pd);
  int* off_dp = (int*)sym(g_off_dp);
  int* off_pd = (int*)sym(g_off_pd);
  int* bsum   = (int*)sym(g_bsum);
  int* bscan  = (int*)sym(g_bscan);
  int* ssrc_dp= (int*)sym(g_ssrc_dp);
  int* ssrc_pd= (int*)sym(g_ssrc_pd);

  const int ZB = (NN + 255) / 256;
  const int EB = (EE + 255) / 256;
  const int SB = (NN + 511) / 512;          // 196 scan blocks
  const int GB = (NN + 63) / 64;            // 1563 gemm blocks
  const int WB = (NN * 32 + 255) / 256;     // 12500 warp-per-node blocks

  // ---- CSR build (both etypes) ----
  zero4_kernel<<<ZB, 256>>>(deg_dp, deg_pd, cur_dp, cur_pd, NN);
  degree_kernel<<<EB, 256>>>(dst_dp, deg_dp, EE);
  degree_kernel<<<EB, 256>>>(dst_pd, deg_pd, EE);

  scan_block_kernel<<<SB, 512>>>(deg_dp, off_dp, bsum, NN);
  scan_block_kernel<<<1, 512>>>(bsum, bscan, nullptr, SB);
  scan_add_kernel<<<SB, 512>>>(off_dp, bscan, NN);

  scan_block_kernel<<<SB, 512>>>(deg_pd, off_pd, bsum, NN);
  scan_block_kernel<<<1, 512>>>(bsum, bscan, nullptr, SB);
  scan_add_kernel<<<SB, 512>>>(off_pd, bscan, NN);

  scatter_kernel<<<EB, 256>>>(src_dp, dst_dp, off_dp, cur_dp, ssrc_dp, EE);
  scatter_kernel<<<EB, 256>>>(src_pd, dst_pd, off_pd, cur_pd, ssrc_pd, EE);

  // ---- input projections (relu) ----
  gemm128_kernel<true><<<GB, 256>>>(x_drug, W_in_d, b_in_d, h_d, NN);
  gemm128_kernel<true><<<GB, 256>>>(x_prot, W_in_p, b_in_p, h_p, NN);

  // ---- GAT feature projections (no bias) ----
  gemm128_kernel<false><<<GB, 256>>>(h_d, W_dp, nullptr, Fd_dp, NN);
  gemm128_kernel<false><<<GB, 256>>>(h_p, W_dp, nullptr, Fp_dp, NN);
  gemm128_kernel<false><<<GB, 256>>>(h_p, W_pd, nullptr, Fp_pd, NN);
  gemm128_kernel<false><<<GB, 256>>>(h_d, W_pd, nullptr, Fd_pd, NN);

  // ---- attention scores ----
  attn_score_kernel<<<WB, 256>>>(Fd_dp, al_dp, el_d_dp, NN);
  attn_score_kernel<<<WB, 256>>>(Fp_dp, ar_dp, er_p_dp, NN);
  attn_score_kernel<<<WB, 256>>>(Fp_pd, al_pd, el_p_pd, NN);
  attn_score_kernel<<<WB, 256>>>(Fd_pd, ar_dp == nullptr ? ar_pd : ar_pd, er_d_pd, NN);

  // ---- edge softmax + aggregation ----
  // dp: drug(src) -> protein(dst)
  gat_agg_kernel<<<WB, 256>>>(off_dp, ssrc_dp, el_d_dp, er_p_dp, Fd_dp,
                              bias_dp, agg_p, NN, EE);
  // pd: protein(src) -> drug(dst)
  gat_agg_kernel<<<WB, 256>>>(off_pd, ssrc_pd, el_p_pd, er_d_pd, Fp_pd,
                              bias_pd, agg_d, NN, EE);

  // ---- output projections, straight into d_out (drug first, then prot) ----
  gemm128_kernel<false><<<GB, 256>>>(agg_d, W_out_d, b_out_d, out, NN);
  gemm128_kernel<false><<<GB, 256>>>(agg_p, W_out_p, b_out_p, out + (size_t)NN * 128, NN);
}

// round 8
// speedup vs baseline: 1.1337x; 1.1337x over previous
#include <cuda_runtime.h>
#include <cuda_bf16.h>
#include <math.h>

#define NN 100000
#define EE 800000
#define HIDC 128

// ---------------- scratch (device globals; no allocations allowed) ----------
__device__ float g_h_d[NN * HIDC];
__device__ float g_h_p[NN * HIDC];
__device__ float g_Fd_dp[NN * HIDC];
__device__ float g_Fp_dp[NN * HIDC];
__device__ float g_Fp_pd[NN * HIDC];
__device__ float g_Fd_pd[NN * HIDC];
__device__ float g_agg_d[NN * HIDC];
__device__ float g_agg_p[NN * HIDC];

__device__ float g_el_d_dp[NN * 4];
__device__ float g_er_p_dp[NN * 4];
__device__ float g_el_p_pd[NN * 4];
__device__ float g_er_d_pd[NN * 4];

// CSR for both etypes, concatenated: [0,NN) = dp (dst=protein),
// [NN,2NN) = pd (dst=drug). Edge slots: dp -> [0,EE), pd -> [EE,2EE).
__device__ int g_deg[2 * NN];
__device__ int g_cur[2 * NN];
__device__ int g_off[2 * NN];
__device__ int g_bsum[512];
__device__ int g_bscan[512];
__device__ int g_ssrc[2 * EE];

// ---------------- packed fp32x2 FMA (Blackwell FFMA2; PTX-only path) --------
__device__ __forceinline__ void fma2(float2& d, float2 a, float2 b) {
  asm("fma.rn.f32x2 %0, %1, %2, %0;"
      : "+l"(reinterpret_cast<unsigned long long&>(d))
      : "l"(reinterpret_cast<unsigned long long&>(a)),
        "l"(reinterpret_cast<unsigned long long&>(b)));
}

// ---------------- GEMM: C[M,128] = A[M,128] @ W[128,128] (+bias)(+relu) -----
// BM=64, BN=128, 256 threads. Thread tile = 8 rows x 4 cols, cols as two
// adjacent PAIRS at {2tc, 2tc+1} and {64+2tc, 64+2tc+1} so B pairs come from
// a single LDS.64 and the packed fma.rn.f32x2 runs with zero pack overhead.
// A tile is staged DUPLICATED in smem as float2 (a,a): one broadcast LDS.64
// yields the packed A operand. Optionally fuses the GAT attention score
// el[n][h] = sum_d F[n,h,d]*avec[h,d] into the epilogue (for bias-free GEMMs).
template <bool RELU>
__global__ __launch_bounds__(256, 2) void gemm128_kernel(
    const float* __restrict__ A, const float* __restrict__ W,
    const float* __restrict__ bias, float* __restrict__ C,
    const float* __restrict__ avec, float* __restrict__ el_out, int M) {
  __shared__ float2 As2[32 * 65];  // As2[kk*65 + r] = (A[r][k], A[r][k])
  __shared__ float Ws[32 * 128];   // Ws[kk*128 + c]
  const int tid = threadIdx.x;
  const int tr = tid >> 5;   // 0..7 row group
  const int tc = tid & 31;   // lane
  const int row0 = blockIdx.x * 64;

  float2 acc[8][2];
#pragma unroll
  for (int i = 0; i < 8; i++) {
    acc[i][0] = make_float2(0.f, 0.f);
    acc[i][1] = make_float2(0.f, 0.f);
  }

  for (int kc = 0; kc < 128; kc += 32) {
    // stage A chunk duplicated: 64 rows x 32 k
#pragma unroll
    for (int t = 0; t < 8; t++) {
      int idx = t * 256 + tid;
      int r = idx >> 5, kk = idx & 31;
      int row = row0 + r;
      float v = (row < M) ? A[row * 128 + kc + kk] : 0.f;
      As2[kk * 65 + r] = make_float2(v, v);
    }
    // stage W chunk: rows [kc,kc+32) contiguous, 4096 floats
    {
      const float4* Wg = reinterpret_cast<const float4*>(W + kc * 128);
      float4* Wsv = reinterpret_cast<float4*>(Ws);
#pragma unroll
      for (int t = 0; t < 4; t++) Wsv[t * 256 + tid] = Wg[t * 256 + tid];
    }
    __syncthreads();

#pragma unroll 8
    for (int kk = 0; kk < 32; kk++) {
      float2 b0 = *reinterpret_cast<const float2*>(&Ws[kk * 128 + 2 * tc]);
      float2 b1 = *reinterpret_cast<const float2*>(&Ws[kk * 128 + 64 + 2 * tc]);
#pragma unroll
      for (int i = 0; i < 8; i++) {
        float2 a = As2[kk * 65 + tr * 8 + i];
        fma2(acc[i][0], a, b0);
        fma2(acc[i][1], a, b1);
      }
    }
    __syncthreads();
  }

  float2 bias0 = make_float2(0.f, 0.f), bias1 = make_float2(0.f, 0.f);
  if (bias) {
    bias0 = *reinterpret_cast<const float2*>(&bias[2 * tc]);
    bias1 = *reinterpret_cast<const float2*>(&bias[64 + 2 * tc]);
  }
  float2 av0 = make_float2(0.f, 0.f), av1 = make_float2(0.f, 0.f);
  if (el_out) {
    av0 = *reinterpret_cast<const float2*>(&avec[2 * tc]);
    av1 = *reinterpret_cast<const float2*>(&avec[64 + 2 * tc]);
  }

#pragma unroll
  for (int i = 0; i < 8; i++) {
    int row = row0 + tr * 8 + i;
    bool ok = (row < M);
    float2 v0 = acc[i][0], v1 = acc[i][1];
    if (bias) { v0.x += bias0.x; v0.y += bias0.y; v1.x += bias1.x; v1.y += bias1.y; }
    if (RELU) {
      v0.x = fmaxf(v0.x, 0.f); v0.y = fmaxf(v0.y, 0.f);
      v1.x = fmaxf(v1.x, 0.f); v1.y = fmaxf(v1.y, 0.f);
    }
    if (ok) {
      *reinterpret_cast<float2*>(&C[row * 128 + 2 * tc]) = v0;
      *reinterpret_cast<float2*>(&C[row * 128 + 64 + 2 * tc]) = v1;
    }
    if (el_out) {
      // heads: cols [0,32)h0 [32,64)h1 [64,96)h2 [96,128)h3.
      // this lane: pair0 in head (tc>>4), pair1 in head 2+(tc>>4).
      float pa = acc[i][0].x * av0.x + acc[i][0].y * av0.y;
      float pb = acc[i][1].x * av1.x + acc[i][1].y * av1.y;
#pragma unroll
      for (int o = 8; o; o >>= 1) {
        pa += __shfl_xor_sync(0xffffffffu, pa, o);
        pb += __shfl_xor_sync(0xffffffffu, pb, o);
      }
      if ((tc & 15) == 0 && ok) {
        int ha = tc >> 4;
        el_out[row * 4 + ha] = pa;
        el_out[row * 4 + 2 + ha] = pb;
      }
    }
  }
}

// ---------------- CSR build (both etypes in one pass) ----------------------
__global__ void zero2_kernel(int* a, int* b, int n) {
  int i = blockIdx.x * blockDim.x + threadIdx.x;
  if (i < n) { a[i] = 0; b[i] = 0; }
}

__global__ void degree2_kernel(const int* __restrict__ dst_dp,
                               const int* __restrict__ dst_pd,
                               int* __restrict__ deg) {
  int i = blockIdx.x * blockDim.x + threadIdx.x;
  if (i < 2 * EE) {
    int nidx = (i < EE) ? dst_dp[i] : (NN + dst_pd[i - EE]);
    atomicAdd(&deg[nidx], 1);
  }
}

__global__ void scan_block_kernel(const int* __restrict__ in,
                                  int* __restrict__ outExcl,
                                  int* __restrict__ bsums, int n) {
  __shared__ int s[512];
  int tid = threadIdx.x;
  int i = blockIdx.x * 512 + tid;
  int v = (i < n) ? in[i] : 0;
  s[tid] = v;
  __syncthreads();
  for (int off = 1; off < 512; off <<= 1) {
    int t = (tid >= off) ? s[tid - off] : 0;
    __syncthreads();
    s[tid] += t;
    __syncthreads();
  }
  if (i < n) outExcl[i] = s[tid] - v;
  if (tid == 511 && bsums) bsums[blockIdx.x] = s[511];
}

__global__ void scan_add_kernel(int* __restrict__ outExcl,
                                const int* __restrict__ bscan, int n) {
  int i = blockIdx.x * 512 + threadIdx.x;
  if (i < n) outExcl[i] += bscan[blockIdx.x];
}

__global__ void scatter2_kernel(const int* __restrict__ src_dp,
                                const int* __restrict__ dst_dp,
                                const int* __restrict__ src_pd,
                                const int* __restrict__ dst_pd,
                                const int* __restrict__ off,
                                int* __restrict__ cur, int* __restrict__ ssrc) {
  int i = blockIdx.x * blockDim.x + threadIdx.x;
  if (i < 2 * EE) {
    int s, nidx;
    if (i < EE) { s = src_dp[i]; nidx = dst_dp[i]; }
    else        { s = src_pd[i - EE]; nidx = NN + dst_pd[i - EE]; }
    int p = atomicAdd(&cur[nidx], 1);
    ssrc[off[nidx] + p] = s;
  }
}

// ---------------- GAT aggregation: one warp per dst node -------------------
// pass 1: online softmax stats (per-lane strided, warp-combined)
// pass 2: lane owns 4 contiguous feature cols (head = lane>>3): one LDG.128
//         per lane per edge, single-head exp per lane.
__global__ void gat_agg_kernel(const int* __restrict__ off,
                               const int* __restrict__ ssrc,
                               const float* __restrict__ el,
                               const float* __restrict__ er,
                               const float* __restrict__ Fsrc,
                               const float* __restrict__ bias,
                               float* __restrict__ out,
                               int nodeBase, int endCap, int n) {
  int w = (blockIdx.x * blockDim.x + threadIdx.x) >> 5;
  int lane = threadIdx.x & 31;
  if (w >= n) return;

  int idx = nodeBase + w;
  int beg = off[idx];
  int end = (idx + 1 < 2 * NN) ? off[idx + 1] : endCap;

  const float4* elv = reinterpret_cast<const float4*>(el);
  float4 erv = reinterpret_cast<const float4*>(er)[w];

  const float NEG = -1e30f;
  float m0 = NEG, m1 = NEG, m2 = NEG, m3 = NEG;
  float s0 = 0.f, s1 = 0.f, s2 = 0.f, s3 = 0.f;

  for (int i = beg + lane; i < end; i += 32) {
    int sp = ssrc[i];
    float4 v = elv[sp];
    float e0 = v.x + erv.x; e0 = (e0 > 0.f) ? e0 : 0.2f * e0;
    float e1 = v.y + erv.y; e1 = (e1 > 0.f) ? e1 : 0.2f * e1;
    float e2 = v.z + erv.z; e2 = (e2 > 0.f) ? e2 : 0.2f * e2;
    float e3 = v.w + erv.w; e3 = (e3 > 0.f) ? e3 : 0.2f * e3;
    float nm;
    nm = fmaxf(m0, e0); s0 = s0 * __expf(m0 - nm) + __expf(e0 - nm); m0 = nm;
    nm = fmaxf(m1, e1); s1 = s1 * __expf(m1 - nm) + __expf(e1 - nm); m1 = nm;
    nm = fmaxf(m2, e2); s2 = s2 * __expf(m2 - nm) + __expf(e2 - nm); m2 = nm;
    nm = fmaxf(m3, e3); s3 = s3 * __expf(m3 - nm) + __expf(e3 - nm); m3 = nm;
  }
  float M0 = m0, M1 = m1, M2 = m2, M3 = m3;
#pragma unroll
  for (int o = 16; o; o >>= 1) {
    M0 = fmaxf(M0, __shfl_xor_sync(0xffffffffu, M0, o));
    M1 = fmaxf(M1, __shfl_xor_sync(0xffffffffu, M1, o));
    M2 = fmaxf(M2, __shfl_xor_sync(0xffffffffu, M2, o));
    M3 = fmaxf(M3, __shfl_xor_sync(0xffffffffu, M3, o));
  }
  float t0 = s0 * __expf(m0 - M0);
  float t1 = s1 * __expf(m1 - M1);
  float t2 = s2 * __expf(m2 - M2);
  float t3 = s3 * __expf(m3 - M3);
#pragma unroll
  for (int o = 16; o; o >>= 1) {
    t0 += __shfl_xor_sync(0xffffffffu, t0, o);
    t1 += __shfl_xor_sync(0xffffffffu, t1, o);
    t2 += __shfl_xor_sync(0xffffffffu, t2, o);
    t3 += __shfl_xor_sync(0xffffffffu, t3, o);
  }

  // per-lane head selection (hoisted out of the edge loop)
  int h = lane >> 3;
  float Mh = (h == 0) ? M0 : (h == 1) ? M1 : (h == 2) ? M2 : M3;
  float th = (h == 0) ? t0 : (h == 1) ? t1 : (h == 2) ? t2 : t3;
  float erh = (h == 0) ? erv.x : (h == 1) ? erv.y : (h == 2) ? erv.z : erv.w;
  float rh = 1.0f / th;

  float4 accv = make_float4(0.f, 0.f, 0.f, 0.f);
  for (int i = beg; i < end; i++) {
    int sp = ssrc[i];  // uniform across warp -> broadcast
    float4 v = elv[sp];
    float e = (h == 0) ? v.x : (h == 1) ? v.y : (h == 2) ? v.z : v.w;
    e += erh;
    e = (e > 0.f) ? e : 0.2f * e;
    float c = __expf(e - Mh) * rh;
    float4 f = reinterpret_cast<const float4*>(Fsrc + sp * 128)[lane];
    accv.x = fmaf(c, f.x, accv.x);
    accv.y = fmaf(c, f.y, accv.y);
    accv.z = fmaf(c, f.z, accv.z);
    accv.w = fmaf(c, f.w, accv.w);
  }
  float4 bv = reinterpret_cast<const float4*>(bias)[lane];
  accv.x += bv.x; accv.y += bv.y; accv.z += bv.z; accv.w += bv.w;
  reinterpret_cast<float4*>(out + w * 128)[lane] = accv;
}

// ---------------- launch ---------------------------------------------------
static inline void* sym(const void* s) {
  void* p = nullptr;
  cudaGetSymbolAddress(&p, s);
  return p;
}

extern "C" void kernel_launch(void* const* d_in, const int* in_sizes, int n_in,
                              void* d_out, int out_size) {
  const float* x_drug = (const float*)d_in[0];
  const float* x_prot = (const float*)d_in[1];
  const int* src_dp = (const int*)d_in[2];
  const int* dst_dp = (const int*)d_in[3];
  const int* src_pd = (const int*)d_in[4];
  const int* dst_pd = (const int*)d_in[5];
  const float* W_in_d = (const float*)d_in[6];
  const float* b_in_d = (const float*)d_in[7];
  const float* W_in_p = (const float*)d_in[8];
  const float* b_in_p = (const float*)d_in[9];
  const float* W_dp   = (const float*)d_in[10];
  const float* al_dp  = (const float*)d_in[11];
  const float* ar_dp  = (const float*)d_in[12];
  const float* bias_dp= (const float*)d_in[13];
  const float* W_pd   = (const float*)d_in[14];
  const float* al_pd  = (const float*)d_in[15];
  const float* ar_pd  = (const float*)d_in[16];
  const float* bias_pd= (const float*)d_in[17];
  const float* W_out_d= (const float*)d_in[18];
  const float* b_out_d= (const float*)d_in[19];
  const float* W_out_p= (const float*)d_in[20];
  const float* b_out_p= (const float*)d_in[21];
  float* out = (float*)d_out;

  float* h_d  = (float*)sym(g_h_d);
  float* h_p  = (float*)sym(g_h_p);
  float* Fd_dp= (float*)sym(g_Fd_dp);
  float* Fp_dp= (float*)sym(g_Fp_dp);
  float* Fp_pd= (float*)sym(g_Fp_pd);
  float* Fd_pd= (float*)sym(g_Fd_pd);
  float* agg_d= (float*)sym(g_agg_d);
  float* agg_p= (float*)sym(g_agg_p);
  float* el_d_dp = (float*)sym(g_el_d_dp);
  float* er_p_dp = (float*)sym(g_er_p_dp);
  float* el_p_pd = (float*)sym(g_el_p_pd);
  float* er_d_pd = (float*)sym(g_er_d_pd);
  int* deg  = (int*)sym(g_deg);
  int* cur  = (int*)sym(g_cur);
  int* off  = (int*)sym(g_off);
  int* bsum = (int*)sym(g_bsum);
  int* bscan= (int*)sym(g_bscan);
  int* ssrc = (int*)sym(g_ssrc);

  const int ZB  = (2 * NN + 255) / 256;
  const int EB2 = (2 * EE + 255) / 256;
  const int SB2 = (2 * NN + 511) / 512;     // 391 scan blocks
  const int GB  = (NN + 63) / 64;           // 1563 gemm blocks
  const int WB  = (NN * 32 + 255) / 256;    // 12500 warp-per-node blocks

  // ---- CSR build (both etypes, concatenated) ----
  zero2_kernel<<<ZB, 256>>>(deg, cur, 2 * NN);
  degree2_kernel<<<EB2, 256>>>(dst_dp, dst_pd, deg);
  scan_block_kernel<<<SB2, 512>>>(deg, off, bsum, 2 * NN);
  scan_block_kernel<<<1, 512>>>(bsum, bscan, nullptr, SB2);
  scan_add_kernel<<<SB2, 512>>>(off, bscan, 2 * NN);
  scatter2_kernel<<<EB2, 256>>>(src_dp, dst_dp, src_pd, dst_pd, off, cur, ssrc);

  // ---- input projections (relu) ----
  gemm128_kernel<true><<<GB, 256>>>(x_drug, W_in_d, b_in_d, h_d, nullptr, nullptr, NN);
  gemm128_kernel<true><<<GB, 256>>>(x_prot, W_in_p, b_in_p, h_p, nullptr, nullptr, NN);

  // ---- GAT feature projections with fused attention scores ----
  gemm128_kernel<false><<<GB, 256>>>(h_d, W_dp, nullptr, Fd_dp, al_dp, el_d_dp, NN);
  gemm128_kernel<false><<<GB, 256>>>(h_p, W_dp, nullptr, Fp_dp, ar_dp, er_p_dp, NN);
  gemm128_kernel<false><<<GB, 256>>>(h_p, W_pd, nullptr, Fp_pd, al_pd, el_p_pd, NN);
  gemm128_kernel<false><<<GB, 256>>>(h_d, W_pd, nullptr, Fd_pd, ar_pd, er_d_pd, NN);

  // ---- edge softmax + aggregation ----
  // dp: drug(src) -> protein(dst); CSR segment [0,NN), edges [0,EE)
  gat_agg_kernel<<<WB, 256>>>(off, ssrc, el_d_dp, er_p_dp, Fd_dp,
                              bias_dp, agg_p, 0, 2 * EE, NN);
  // pd: protein(src) -> drug(dst); CSR segment [NN,2NN), edges [EE,2EE)
  gat_agg_kernel<<<WB, 256>>>(off, ssrc, el_p_pd, er_d_pd, Fp_pd,
                              bias_pd, agg_d, NN, 2 * EE, NN);

  // ---- output projections, straight into d_out (drug first, then prot) ----
  gemm128_kernel<false><<<GB, 256>>>(agg_d, W_out_d, b_out_d, out, nullptr, nullptr, NN);
  gemm128_kernel<false><<<GB, 256>>>(agg_p, W_out_p, b_out_p, out + (size_t)NN * 128, nullptr, nullptr, NN);
}

// round 10
// speedup vs baseline: 1.1951x; 1.0541x over previous
#include <cuda_runtime.h>
#include <cuda_bf16.h>
#include <math.h>

#define NN 100000
#define EE 800000
#define HIDC 128

// ---------------- scratch (device globals; no allocations allowed) ----------
__device__ float g_h_d[NN * HIDC];
__device__ float g_h_p[NN * HIDC];
__device__ float g_Fd_dp[NN * HIDC];
__device__ float g_Fp_dp[NN * HIDC];
__device__ float g_Fp_pd[NN * HIDC];
__device__ float g_Fd_pd[NN * HIDC];
__device__ float g_agg_d[NN * HIDC];
__device__ float g_agg_p[NN * HIDC];

__device__ float g_el_d_dp[NN * 4];
__device__ float g_er_p_dp[NN * 4];
__device__ float g_el_p_pd[NN * 4];
__device__ float g_er_d_pd[NN * 4];

// CSR for both etypes, concatenated: [0,NN) = dp (dst=protein),
// [NN,2NN) = pd (dst=drug). Edge slots: dp -> [0,EE), pd -> [EE,2EE).
__device__ int g_deg[2 * NN];
__device__ int g_cur[2 * NN];
__device__ int g_off[2 * NN];
__device__ int g_bsum[512];
__device__ int g_bscan[512];
__device__ int g_ssrc[2 * EE];

// ---------------- packed fp32x2 FMA (Blackwell FFMA2; PTX-only path) --------
__device__ __forceinline__ void fma2(float2& d, float2 a, float2 b) {
  asm("fma.rn.f32x2 %0, %1, %2, %0;"
      : "+l"(reinterpret_cast<unsigned long long&>(d))
      : "l"(reinterpret_cast<unsigned long long&>(a)),
        "l"(reinterpret_cast<unsigned long long&>(b)));
}

// ---------------- GEMM: C[M,128] = A[M,128] @ W[128,128] (+bias)(+relu) -----
// BM=128, BN=128, 256 threads, 8x8 thread tile. A tile transposed in smem
// (stride 132: float4-aligned, 4-way store conflict accepted, store traffic
// is 1/8 of load traffic). f32x2 pairs packed along M: two consecutive rows
// come from one LDS.128 as a natural register pair; B scalars duplicated via
// cheap MOVs (alu pipe, overlapped). Per thread per kk: 4 LDS.128 + 32 FFMA2
// -> fma-pipe bound. Optionally fuses attention score el[n][h] into epilogue.
#define ASTRIDE 132
template <bool RELU>
__global__ __launch_bounds__(256, 2) void gemm128_kernel(
    const float* __restrict__ A, const float* __restrict__ W,
    const float* __restrict__ bias, float* __restrict__ C,
    const float* __restrict__ avec, float* __restrict__ el_out, int M) {
  __shared__ __align__(16) float As[32 * ASTRIDE];  // As[kk*132 + r]
  __shared__ __align__(16) float Ws[32 * 128];      // Ws[kk*128 + c]
  const int tid = threadIdx.x;
  const int ty = tid >> 4;   // 0..15 (row group, 8 rows each)
  const int tx = tid & 15;   // 0..15 (col group, 8 cols each)
  const int row0 = blockIdx.x * 128;

  // acc[p][c] = (row0+ty*8+2p, row0+ty*8+2p+1) x col (tx*8+c)
  float2 acc[4][8];
#pragma unroll
  for (int p = 0; p < 4; p++)
#pragma unroll
    for (int c = 0; c < 8; c++) acc[p][c] = make_float2(0.f, 0.f);

  for (int kc = 0; kc < 128; kc += 32) {
    // stage A chunk transposed: 128 rows x 32 k (coalesced gmem reads)
#pragma unroll
    for (int t = 0; t < 16; t++) {
      int idx = t * 256 + tid;          // 0..4095
      int r = idx >> 5, kk = idx & 31;
      int row = row0 + r;
      float v = (row < M) ? A[row * 128 + kc + kk] : 0.f;
      As[kk * ASTRIDE + r] = v;
    }
    // stage W chunk: rows [kc,kc+32) contiguous, 4096 floats
    {
      const float4* Wg = reinterpret_cast<const float4*>(W + kc * 128);
      float4* Wsv = reinterpret_cast<float4*>(Ws);
#pragma unroll
      for (int t = 0; t < 4; t++) Wsv[t * 256 + tid] = Wg[t * 256 + tid];
    }
    __syncthreads();

#pragma unroll 4
    for (int kk = 0; kk < 32; kk++) {
      float4 a0 = *reinterpret_cast<const float4*>(&As[kk * ASTRIDE + ty * 8]);
      float4 a1 = *reinterpret_cast<const float4*>(&As[kk * ASTRIDE + ty * 8 + 4]);
      float4 b0 = *reinterpret_cast<const float4*>(&Ws[kk * 128 + tx * 8]);
      float4 b1 = *reinterpret_cast<const float4*>(&Ws[kk * 128 + tx * 8 + 4]);
      float2 ap[4];
      ap[0] = make_float2(a0.x, a0.y);
      ap[1] = make_float2(a0.z, a0.w);
      ap[2] = make_float2(a1.x, a1.y);
      ap[3] = make_float2(a1.z, a1.w);
      float bs[8] = {b0.x, b0.y, b0.z, b0.w, b1.x, b1.y, b1.z, b1.w};
#pragma unroll
      for (int c = 0; c < 8; c++) {
        float2 bb = make_float2(bs[c], bs[c]);
#pragma unroll
        for (int p = 0; p < 4; p++) fma2(acc[p][c], ap[p], bb);
      }
    }
    __syncthreads();
  }

  // epilogue
  float bs8[8];
  if (bias) {
#pragma unroll
    for (int c = 0; c < 8; c++) bs8[c] = bias[tx * 8 + c];
  }

#pragma unroll
  for (int p = 0; p < 4; p++) {
    int ra = row0 + ty * 8 + 2 * p;
    int rb = ra + 1;
    float va[8], vb[8];
#pragma unroll
    for (int c = 0; c < 8; c++) {
      va[c] = acc[p][c].x;
      vb[c] = acc[p][c].y;
      if (bias) { va[c] += bs8[c]; vb[c] += bs8[c]; }
      if (RELU) { va[c] = fmaxf(va[c], 0.f); vb[c] = fmaxf(vb[c], 0.f); }
    }
    if (ra < M) {
      *reinterpret_cast<float4*>(&C[ra * 128 + tx * 8]) =
          make_float4(va[0], va[1], va[2], va[3]);
      *reinterpret_cast<float4*>(&C[ra * 128 + tx * 8 + 4]) =
          make_float4(va[4], va[5], va[6], va[7]);
    }
    if (rb < M) {
      *reinterpret_cast<float4*>(&C[rb * 128 + tx * 8]) =
          make_float4(vb[0], vb[1], vb[2], vb[3]);
      *reinterpret_cast<float4*>(&C[rb * 128 + tx * 8 + 4]) =
          make_float4(vb[4], vb[5], vb[6], vb[7]);
    }
  }

  if (el_out) {
    // this thread's 8 cols [tx*8, tx*8+8) lie entirely in head h = tx>>2.
    // el[row][h] = sum over cols of acc * avec; reduce over the 4 tx lanes
    // of the head group (consecutive lanes in the warp).
    float av[8];
#pragma unroll
    for (int c = 0; c < 8; c++) av[c] = avec[tx * 8 + c];
    int h = tx >> 2;
#pragma unroll
    for (int p = 0; p < 4; p++) {
      float pa = 0.f, pb = 0.f;
#pragma unroll
      for (int c = 0; c < 8; c++) {
        pa = fmaf(acc[p][c].x, av[c], pa);
        pb = fmaf(acc[p][c].y, av[c], pb);
      }
#pragma unroll
      for (int o = 1; o < 4; o <<= 1) {
        pa += __shfl_xor_sync(0xffffffffu, pa, o);
        pb += __shfl_xor_sync(0xffffffffu, pb, o);
      }
      if ((tx & 3) == 0) {
        int ra = row0 + ty * 8 + 2 * p;
        if (ra < M) el_out[ra * 4 + h] = pa;
        if (ra + 1 < M) el_out[(ra + 1) * 4 + h] = pb;
      }
    }
  }
}

// ---------------- CSR build (both etypes in one pass) ----------------------
__global__ void zero2_kernel(int* a, int* b, int n) {
  int i = blockIdx.x * blockDim.x + threadIdx.x;
  if (i < n) { a[i] = 0; b[i] = 0; }
}

__global__ void degree2_kernel(const int* __restrict__ dst_dp,
                               const int* __restrict__ dst_pd,
                               int* __restrict__ deg) {
  int i = blockIdx.x * blockDim.x + threadIdx.x;
  if (i < 2 * EE) {
    int nidx = (i < EE) ? dst_dp[i] : (NN + dst_pd[i - EE]);
    atomicAdd(&deg[nidx], 1);
  }
}

__global__ void scan_block_kernel(const int* __restrict__ in,
                                  int* __restrict__ outExcl,
                                  int* __restrict__ bsums, int n) {
  __shared__ int s[512];
  int tid = threadIdx.x;
  int i = blockIdx.x * 512 + tid;
  int v = (i < n) ? in[i] : 0;
  s[tid] = v;
  __syncthreads();
  for (int off = 1; off < 512; off <<= 1) {
    int t = (tid >= off) ? s[tid - off] : 0;
    __syncthreads();
    s[tid] += t;
    __syncthreads();
  }
  if (i < n) outExcl[i] = s[tid] - v;
  if (tid == 511 && bsums) bsums[blockIdx.x] = s[511];
}

__global__ void scan_add_kernel(int* __restrict__ outExcl,
                                const int* __restrict__ bscan, int n) {
  int i = blockIdx.x * 512 + threadIdx.x;
  if (i < n) outExcl[i] += bscan[blockIdx.x];
}

__global__ void scatter2_kernel(const int* __restrict__ src_dp,
                                const int* __restrict__ dst_dp,
                                const int* __restrict__ src_pd,
                                const int* __restrict__ dst_pd,
                                const int* __restrict__ off,
                                int* __restrict__ cur, int* __restrict__ ssrc) {
  int i = blockIdx.x * blockDim.x + threadIdx.x;
  if (i < 2 * EE) {
    int s, nidx;
    if (i < EE) { s = src_dp[i]; nidx = dst_dp[i]; }
    else        { s = src_pd[i - EE]; nidx = NN + dst_pd[i - EE]; }
    int p = atomicAdd(&cur[nidx], 1);
    ssrc[off[nidx] + p] = s;
  }
}

// ---------------- GAT aggregation: one warp per dst node -------------------
__global__ void gat_agg_kernel(const int* __restrict__ off,
                               const int* __restrict__ ssrc,
                               const float* __restrict__ el,
                               const float* __restrict__ er,
                               const float* __restrict__ Fsrc,
                               const float* __restrict__ bias,
                               float* __restrict__ out,
                               int nodeBase, int endCap, int n) {
  int w = (blockIdx.x * blockDim.x + threadIdx.x) >> 5;
  int lane = threadIdx.x & 31;
  if (w >= n) return;

  int idx = nodeBase + w;
  int beg = off[idx];
  int end = (idx + 1 < 2 * NN) ? off[idx + 1] : endCap;

  const float4* elv = reinterpret_cast<const float4*>(el);
  float4 erv = reinterpret_cast<const float4*>(er)[w];

  const float NEG = -1e30f;
  float m0 = NEG, m1 = NEG, m2 = NEG, m3 = NEG;
  float s0 = 0.f, s1 = 0.f, s2 = 0.f, s3 = 0.f;

  for (int i = beg + lane; i < end; i += 32) {
    int sp = ssrc[i];
    float4 v = elv[sp];
    float e0 = v.x + erv.x; e0 = (e0 > 0.f) ? e0 : 0.2f * e0;
    float e1 = v.y + erv.y; e1 = (e1 > 0.f) ? e1 : 0.2f * e1;
    float e2 = v.z + erv.z; e2 = (e2 > 0.f) ? e2 : 0.2f * e2;
    float e3 = v.w + erv.w; e3 = (e3 > 0.f) ? e3 : 0.2f * e3;
    float nm;
    nm = fmaxf(m0, e0); s0 = s0 * __expf(m0 - nm) + __expf(e0 - nm); m0 = nm;
    nm = fmaxf(m1, e1); s1 = s1 * __expf(m1 - nm) + __expf(e1 - nm); m1 = nm;
    nm = fmaxf(m2, e2); s2 = s2 * __expf(m2 - nm) + __expf(e2 - nm); m2 = nm;
    nm = fmaxf(m3, e3); s3 = s3 * __expf(m3 - nm) + __expf(e3 - nm); m3 = nm;
  }
  float M0 = m0, M1 = m1, M2 = m2, M3 = m3;
#pragma unroll
  for (int o = 16; o; o >>= 1) {
    M0 = fmaxf(M0, __shfl_xor_sync(0xffffffffu, M0, o));
    M1 = fmaxf(M1, __shfl_xor_sync(0xffffffffu, M1, o));
    M2 = fmaxf(M2, __shfl_xor_sync(0xffffffffu, M2, o));
    M3 = fmaxf(M3, __shfl_xor_sync(0xffffffffu, M3, o));
  }
  float t0 = s0 * __expf(m0 - M0);
  float t1 = s1 * __expf(m1 - M1);
  float t2 = s2 * __expf(m2 - M2);
  float t3 = s3 * __expf(m3 - M3);
#pragma unroll
  for (int o = 16; o; o >>= 1) {
    t0 += __shfl_xor_sync(0xffffffffu, t0, o);
    t1 += __shfl_xor_sync(0xffffffffu, t1, o);
    t2 += __shfl_xor_sync(0xffffffffu, t2, o);
    t3 += __shfl_xor_sync(0xffffffffu, t3, o);
  }

  int h = lane >> 3;
  float Mh = (h == 0) ? M0 : (h == 1) ? M1 : (h == 2) ? M2 : M3;
  float th = (h == 0) ? t0 : (h == 1) ? t1 : (h == 2) ? t2 : t3;
  float erh = (h == 0) ? erv.x : (h == 1) ? erv.y : (h == 2) ? erv.z : erv.w;
  float rh = 1.0f / th;

  float4 accv = make_float4(0.f, 0.f, 0.f, 0.f);
  for (int i = beg; i < end; i++) {
    int sp = ssrc[i];  // uniform across warp -> broadcast
    float4 v = elv[sp];
    float e = (h == 0) ? v.x : (h == 1) ? v.y : (h == 2) ? v.z : v.w;
    e += erh;
    e = (e > 0.f) ? e : 0.2f * e;
    float c = __expf(e - Mh) * rh;
    float4 f = reinterpret_cast<const float4*>(Fsrc + sp * 128)[lane];
    accv.x = fmaf(c, f.x, accv.x);
    accv.y = fmaf(c, f.y, accv.y);
    accv.z = fmaf(c, f.z, accv.z);
    accv.w = fmaf(c, f.w, accv.w);
  }
  float4 bv = reinterpret_cast<const float4*>(bias)[lane];
  accv.x += bv.x; accv.y += bv.y; accv.z += bv.z; accv.w += bv.w;
  reinterpret_cast<float4*>(out + w * 128)[lane] = accv;
}

// ---------------- launch ---------------------------------------------------
static inline void* sym(const void* s) {
  void* p = nullptr;
  cudaGetSymbolAddress(&p, s);
  return p;
}

extern "C" void kernel_launch(void* const* d_in, const int* in_sizes, int n_in,
                              void* d_out, int out_size) {
  const float* x_drug = (const float*)d_in[0];
  const float* x_prot = (const float*)d_in[1];
  const int* src_dp = (const int*)d_in[2];
  const int* dst_dp = (const int*)d_in[3];
  const int* src_pd = (const int*)d_in[4];
  const int* dst_pd = (const int*)d_in[5];
  const float* W_in_d = (const float*)d_in[6];
  const float* b_in_d = (const float*)d_in[7];
  const float* W_in_p = (const float*)d_in[8];
  const float* b_in_p = (const float*)d_in[9];
  const float* W_dp   = (const float*)d_in[10];
  const float* al_dp  = (const float*)d_in[11];
  const float* ar_dp  = (const float*)d_in[12];
  const float* bias_dp= (const float*)d_in[13];
  const float* W_pd   = (const float*)d_in[14];
  const float* al_pd  = (const float*)d_in[15];
  const float* ar_pd  = (const float*)d_in[16];
  const float* bias_pd= (const float*)d_in[17];
  const float* W_out_d= (const float*)d_in[18];
  const float* b_out_d= (const float*)d_in[19];
  const float* W_out_p= (const float*)d_in[20];
  const float* b_out_p= (const float*)d_in[21];
  float* out = (float*)d_out;

  float* h_d  = (float*)sym(g_h_d);
  float* h_p  = (float*)sym(g_h_p);
  float* Fd_dp= (float*)sym(g_Fd_dp);
  float* Fp_dp= (float*)sym(g_Fp_dp);
  float* Fp_pd= (float*)sym(g_Fp_pd);
  float* Fd_pd= (float*)sym(g_Fd_pd);
  float* agg_d= (float*)sym(g_agg_d);
  float* agg_p= (float*)sym(g_agg_p);
  float* el_d_dp = (float*)sym(g_el_d_dp);
  float* er_p_dp = (float*)sym(g_er_p_dp);
  float* el_p_pd = (float*)sym(g_el_p_pd);
  float* er_d_pd = (float*)sym(g_er_d_pd);
  int* deg  = (int*)sym(g_deg);
  int* cur  = (int*)sym(g_cur);
  int* off  = (int*)sym(g_off);
  int* bsum = (int*)sym(g_bsum);
  int* bscan= (int*)sym(g_bscan);
  int* ssrc = (int*)sym(g_ssrc);

  const int ZB  = (2 * NN + 255) / 256;
  const int EB2 = (2 * EE + 255) / 256;
  const int SB2 = (2 * NN + 511) / 512;     // 391 scan blocks
  const int GB  = (NN + 127) / 128;         // 782 gemm blocks
  const int WB  = (NN * 32 + 255) / 256;    // warp-per-node blocks

  // ---- CSR build (both etypes, concatenated) ----
  zero2_kernel<<<ZB, 256>>>(deg, cur, 2 * NN);
  degree2_kernel<<<EB2, 256>>>(dst_dp, dst_pd, deg);
  scan_block_kernel<<<SB2, 512>>>(deg, off, bsum, 2 * NN);
  scan_block_kernel<<<1, 512>>>(bsum, bscan, nullptr, SB2);
  scan_add_kernel<<<SB2, 512>>>(off, bscan, 2 * NN);
  scatter2_kernel<<<EB2, 256>>>(src_dp, dst_dp, src_pd, dst_pd, off, cur, ssrc);

  // ---- input projections (relu) ----
  gemm128_kernel<true><<<GB, 256>>>(x_drug, W_in_d, b_in_d, h_d, nullptr, nullptr, NN);
  gemm128_kernel<true><<<GB, 256>>>(x_prot, W_in_p, b_in_p, h_p, nullptr, nullptr, NN);

  // ---- GAT feature projections with fused attention scores ----
  gemm128_kernel<false><<<GB, 256>>>(h_d, W_dp, nullptr, Fd_dp, al_dp, el_d_dp, NN);
  gemm128_kernel<false><<<GB, 256>>>(h_p, W_dp, nullptr, Fp_dp, ar_dp, er_p_dp, NN);
  gemm128_kernel<false><<<GB, 256>>>(h_p, W_pd, nullptr, Fp_pd, al_pd, el_p_pd, NN);
  gemm128_kernel<false><<<GB, 256>>>(h_d, W_pd, nullptr, Fd_pd, ar_pd, er_d_pd, NN);

  // ---- edge softmax + aggregation ----
  // dp: drug(src) -> protein(dst); CSR segment [0,NN), edges [0,EE)
  gat_agg_kernel<<<WB, 256>>>(off, ssrc, el_d_dp, er_p_dp, Fd_dp,
                              bias_dp, agg_p, 0, 2 * EE, NN);
  // pd: protein(src) -> drug(dst); CSR segment [NN,2NN), edges [EE,2EE)
  gat_agg_kernel<<<WB, 256>>>(off, ssrc, el_p_pd, er_d_pd, Fp_pd,
                              bias_pd, agg_d, NN, 2 * EE, NN);

  // ---- output projections, straight into d_out (drug first, then prot) ----
  gemm128_kernel<false><<<GB, 256>>>(agg_d, W_out_d, b_out_d, out, nullptr, nullptr, NN);
  gemm128_kernel<false><<<GB, 256>>>(agg_p, W_out_p, b_out_p, out + (size_t)NN * 128, nullptr, nullptr, NN);
}

// round 13
// speedup vs baseline: 1.7494x; 1.4638x over previous
#include <cuda_runtime.h>
#include <cuda_bf16.h>
#include <math.h>
#include <stdint.h>

#define NN 100000
#define EE 800000
#define HIDC 128

// ---------------- scratch (device globals; no allocations allowed) ----------
__device__ float g_h_d[NN * HIDC];
__device__ float g_h_p[NN * HIDC];
__device__ float g_Fd_dp[NN * HIDC];
__device__ float g_Fp_dp[NN * HIDC];
__device__ float g_Fp_pd[NN * HIDC];
__device__ float g_Fd_pd[NN * HIDC];
__device__ float g_agg_d[NN * HIDC];
__device__ float g_agg_p[NN * HIDC];

__device__ float g_el_d_dp[NN * 4];
__device__ float g_er_p_dp[NN * 4];
__device__ float g_el_p_pd[NN * 4];
__device__ float g_er_d_pd[NN * 4];

// CSR for both etypes, concatenated: [0,NN) = dp (dst=protein),
// [NN,2NN) = pd (dst=drug). Edge slots: dp -> [0,EE), pd -> [EE,2EE).
__device__ int g_deg[2 * NN];
__device__ int g_cur[2 * NN];
__device__ int g_off[2 * NN];
__device__ int g_bsum[512];
__device__ int g_bscan[512];
__device__ int g_ssrc[2 * EE];

// Transposed bf16 weight images Bt[n][k] (hi / lo split), 6 matrices 128x128.
__device__ __nv_bfloat16 g_WimgH[6 * 16384];
__device__ __nv_bfloat16 g_WimgL[6 * 16384];

// ---------------- mma.sync helpers (baseline PTX, works at compute_103) -----
__device__ __forceinline__ uint32_t smem_u32(const void* p) {
  uint32_t a;
  asm("{ .reg .u64 t; cvta.to.shared.u64 t, %1; cvt.u32.u64 %0, t; }"
      : "=r"(a) : "l"(p));
  return a;
}

__device__ __forceinline__ void ldm4(uint32_t* r, uint32_t addr) {
  asm volatile(
      "ldmatrix.sync.aligned.m8n8.x4.shared.b16 {%0,%1,%2,%3}, [%4];"
      : "=r"(r[0]), "=r"(r[1]), "=r"(r[2]), "=r"(r[3]) : "r"(addr));
}

__device__ __forceinline__ void mma_bf16(float* c, const uint32_t* a,
                                         uint32_t b0, uint32_t b1) {
  asm volatile(
      "mma.sync.aligned.m16n8k16.row.col.f32.bf16.bf16.f32 "
      "{%0,%1,%2,%3}, {%4,%5,%6,%7}, {%8,%9}, {%0,%1,%2,%3};"
      : "+f"(c[0]), "+f"(c[1]), "+f"(c[2]), "+f"(c[3])
      : "r"(a[0]), "r"(a[1]), "r"(a[2]), "r"(a[3]), "r"(b0), "r"(b1));
}

// SMEM plan: 4 bf16 tiles of 128 rows x 136 bf16 (272B padded stride).
// Stride 272B: row step = 68 words = 4 banks mod 32 -> each ldmatrix 8x16B
// tile covers all 32 banks exactly once (conflict-free).
#define PADB 272
#define SM_AH 0
#define SM_AL (128 * PADB)
#define SM_BH (2 * 128 * PADB)
#define SM_BL (3 * 128 * PADB)
#define SM_TOTAL (4 * 128 * PADB)  // 139264 B

// ---------------- W -> transposed bf16 hi/lo images (one-time) --------------
__global__ void convW_kernel(const float* __restrict__ W0, const float* __restrict__ W1,
                             const float* __restrict__ W2, const float* __restrict__ W3,
                             const float* __restrict__ W4, const float* __restrict__ W5,
                             __nv_bfloat16* __restrict__ imgH,
                             __nv_bfloat16* __restrict__ imgL) {
  int i = blockIdx.x * 256 + threadIdx.x;
  if (i >= 6 * 16384) return;
  int w = i >> 14, idx = i & 16383;
  int n = idx >> 7, k = idx & 127;  // Bt[n][k] = W[k][n]
  const float* Wp = (w == 0) ? W0 : (w == 1) ? W1 : (w == 2) ? W2
                  : (w == 3) ? W3 : (w == 4) ? W4 : W5;
  float v = Wp[k * 128 + n];
  __nv_bfloat16 h = __float2bfloat16(v);
  imgH[w * 16384 + idx] = h;
  imgL[w * 16384 + idx] = __float2bfloat16(v - __bfloat162float(h));
}

// ---------------- tensor-core GEMM via mma.sync (Markidis bf16 split) -------
// C[M,128] = A[M,128] @ W  (+bias)(+relu)(+fused attention score el).
// 128x128 tile/CTA, 256 threads, warp tile 64x32 (warp grid 2x4; warp col
// tile == one attention head). D = Ah*Bh + Ah*Bl + Al*Bh, fp32 accum.
template <bool RELU>
__global__ __launch_bounds__(256, 1) void mma_gemm_kernel(
    const float* __restrict__ A, const __nv_bfloat16* __restrict__ BtH,
    const __nv_bfloat16* __restrict__ BtL, const float* __restrict__ bias,
    float* __restrict__ C, const float* __restrict__ avec,
    float* __restrict__ el_out, int M) {
  extern __shared__ __align__(16) char smem[];
  const uint32_t sb = smem_u32(smem);
  const int tid = threadIdx.x, wid = tid >> 5, lane = tid & 31;
  const int row0 = blockIdx.x * 128;

  // stage B tiles (gmem images are plain [n][128] bf16; pad rows to 272B)
  {
    const float4* bh = reinterpret_cast<const float4*>(BtH);
    const float4* bl = reinterpret_cast<const float4*>(BtL);
#pragma unroll
    for (int t = 0; t < 8; t++) {
      int idx = t * 256 + tid;  // 0..2047
      int r = idx >> 4, q = idx & 15;
      *reinterpret_cast<float4*>(smem + SM_BH + r * PADB + q * 16) = bh[idx];
      *reinterpret_cast<float4*>(smem + SM_BL + r * PADB + q * 16) = bl[idx];
    }
  }
  // stage A tile: load fp32, split hi/lo bf16
#pragma unroll 4
  for (int t = 0; t < 16; t++) {
    int idx = t * 256 + tid;  // 0..4095
    int r = idx >> 5, c4 = idx & 31;
    int g = row0 + r;
    float4 v = (g < M) ? reinterpret_cast<const float4*>(A)[g * 32 + c4]
                       : make_float4(0.f, 0.f, 0.f, 0.f);
    __nv_bfloat162 h01 = __floats2bfloat162_rn(v.x, v.y);
    __nv_bfloat162 h23 = __floats2bfloat162_rn(v.z, v.w);
    __nv_bfloat162 l01 = __floats2bfloat162_rn(v.x - __bfloat162float(h01.x),
                                               v.y - __bfloat162float(h01.y));
    __nv_bfloat162 l23 = __floats2bfloat162_rn(v.z - __bfloat162float(h23.x),
                                               v.w - __bfloat162float(h23.y));
    char* ph = smem + SM_AH + r * PADB + c4 * 8;
    char* pl = smem + SM_AL + r * PADB + c4 * 8;
    *reinterpret_cast<__nv_bfloat162*>(ph) = h01;
    *reinterpret_cast<__nv_bfloat162*>(ph + 4) = h23;
    *reinterpret_cast<__nv_bfloat162*>(pl) = l01;
    *reinterpret_cast<__nv_bfloat162*>(pl + 4) = l23;
  }
  __syncthreads();

  const int wr = wid >> 2, wc = wid & 3;
  const int m0 = wr * 64, n0 = wc * 32;

  float acc[4][4][4];  // [mt(16 rows)][nt(8 cols)][c0..c3]
#pragma unroll
  for (int mt = 0; mt < 4; mt++)
#pragma unroll
    for (int nt = 0; nt < 4; nt++)
#pragma unroll
      for (int c = 0; c < 4; c++) acc[mt][nt][c] = 0.f;

  // per-lane ldmatrix base addresses
  const uint32_t aOff = (uint32_t)(m0 + (lane & 15)) * PADB + ((lane >> 4) << 4);
  const uint32_t aH = sb + SM_AH + aOff;
  const uint32_t aL = sb + SM_AL + aOff;
  const uint32_t bOff =
      (uint32_t)(n0 + (lane & 7) + ((lane >> 4) << 3)) * PADB +
      (((lane >> 3) & 1) << 4);
  const uint32_t bH = sb + SM_BH + bOff;
  const uint32_t bL = sb + SM_BL + bOff;

  // fused passes: Ah*Bh + Ah*Bl (A frags loaded once per kstep)
#pragma unroll
  for (int k = 0; k < 8; k++) {
    const uint32_t ka = (uint32_t)k * 32;  // 16 bf16 = 32 bytes
    uint32_t a[4][4];
#pragma unroll
    for (int mt = 0; mt < 4; mt++) ldm4(a[mt], aH + mt * 16 * PADB + ka);
    uint32_t bh0[4], bh1[4], bl0[4], bl1[4];
    ldm4(bh0, bH + ka);
    ldm4(bh1, bH + 16 * PADB + ka);
    ldm4(bl0, bL + ka);
    ldm4(bl1, bL + 16 * PADB + ka);
#pragma unroll
    for (int mt = 0; mt < 4; mt++) {
      mma_bf16(acc[mt][0], a[mt], bh0[0], bh0[1]);
      mma_bf16(acc[mt][1], a[mt], bh0[2], bh0[3]);
      mma_bf16(acc[mt][2], a[mt], bh1[0], bh1[1]);
      mma_bf16(acc[mt][3], a[mt], bh1[2], bh1[3]);
      mma_bf16(acc[mt][0], a[mt], bl0[0], bl0[1]);
      mma_bf16(acc[mt][1], a[mt], bl0[2], bl0[3]);
      mma_bf16(acc[mt][2], a[mt], bl1[0], bl1[1]);
      mma_bf16(acc[mt][3], a[mt], bl1[2], bl1[3]);
    }
  }
  // pass 3: Al*Bh
#pragma unroll
  for (int k = 0; k < 8; k++) {
    const uint32_t ka = (uint32_t)k * 32;
    uint32_t a[4][4];
#pragma unroll
    for (int mt = 0; mt < 4; mt++) ldm4(a[mt], aL + mt * 16 * PADB + ka);
    uint32_t bh0[4], bh1[4];
    ldm4(bh0, bH + ka);
    ldm4(bh1, bH + 16 * PADB + ka);
#pragma unroll
    for (int mt = 0; mt < 4; mt++) {
      mma_bf16(acc[mt][0], a[mt], bh0[0], bh0[1]);
      mma_bf16(acc[mt][1], a[mt], bh0[2], bh0[3]);
      mma_bf16(acc[mt][2], a[mt], bh1[0], bh1[1]);
      mma_bf16(acc[mt][3], a[mt], bh1[2], bh1[3]);
    }
  }

  // ---- epilogue ----
  const int t4 = lane & 3, g4 = lane >> 2;

  if (el_out) {
    // warp col tile [n0, n0+32) == head wc. el[row][wc] = sum_c F*avec.
    float av0[4], av1[4];
#pragma unroll
    for (int nt = 0; nt < 4; nt++) {
      av0[nt] = avec[n0 + nt * 8 + 2 * t4];
      av1[nt] = avec[n0 + nt * 8 + 2 * t4 + 1];
    }
#pragma unroll
    for (int mt = 0; mt < 4; mt++) {
      float p1 = 0.f, p2 = 0.f;
#pragma unroll
      for (int nt = 0; nt < 4; nt++) {
        p1 = fmaf(acc[mt][nt][0], av0[nt], p1);
        p1 = fmaf(acc[mt][nt][1], av1[nt], p1);
        p2 = fmaf(acc[mt][nt][2], av0[nt], p2);
        p2 = fmaf(acc[mt][nt][3], av1[nt], p2);
      }
      p1 += __shfl_xor_sync(0xffffffffu, p1, 1);
      p1 += __shfl_xor_sync(0xffffffffu, p1, 2);
      p2 += __shfl_xor_sync(0xffffffffu, p2, 1);
      p2 += __shfl_xor_sync(0xffffffffu, p2, 2);
      if (t4 == 0) {
        int r1 = row0 + m0 + mt * 16 + g4;
        if (r1 < M) el_out[r1 * 4 + wc] = p1;
        if (r1 + 8 < M) el_out[(r1 + 8) * 4 + wc] = p2;
      }
    }
  }

  float b0r[4], b1r[4];
  if (bias) {
#pragma unroll
    for (int nt = 0; nt < 4; nt++) {
      b0r[nt] = bias[n0 + nt * 8 + 2 * t4];
      b1r[nt] = bias[n0 + nt * 8 + 2 * t4 + 1];
    }
  }

#pragma unroll
  for (int mt = 0; mt < 4; mt++) {
    int r1 = row0 + m0 + mt * 16 + g4;
    int r2 = r1 + 8;
#pragma unroll
    for (int nt = 0; nt < 4; nt++) {
      int col = n0 + nt * 8 + 2 * t4;
      float2 v1 = make_float2(acc[mt][nt][0], acc[mt][nt][1]);
      float2 v2 = make_float2(acc[mt][nt][2], acc[mt][nt][3]);
      if (bias) {
        v1.x += b0r[nt]; v1.y += b1r[nt];
        v2.x += b0r[nt]; v2.y += b1r[nt];
      }
      if (RELU) {
        v1.x = fmaxf(v1.x, 0.f); v1.y = fmaxf(v1.y, 0.f);
        v2.x = fmaxf(v2.x, 0.f); v2.y = fmaxf(v2.y, 0.f);
      }
      if (r1 < M) *reinterpret_cast<float2*>(&C[r1 * 128 + col]) = v1;
      if (r2 < M) *reinterpret_cast<float2*>(&C[r2 * 128 + col]) = v2;
    }
  }
}

// ---------------- CSR build (both etypes in one pass) ----------------------
__global__ void zero2_kernel(int* a, int* b, int n) {
  int i = blockIdx.x * blockDim.x + threadIdx.x;
  if (i < n) { a[i] = 0; b[i] = 0; }
}

__global__ void degree2_kernel(const int* __restrict__ dst_dp,
                               const int* __restrict__ dst_pd,
                               int* __restrict__ deg) {
  int i = blockIdx.x * blockDim.x + threadIdx.x;
  if (i < 2 * EE) {
    int nidx = (i < EE) ? dst_dp[i] : (NN + dst_pd[i - EE]);
    atomicAdd(&deg[nidx], 1);
  }
}

__global__ void scan_block_kernel(const int* __restrict__ in,
                                  int* __restrict__ outExcl,
                                  int* __restrict__ bsums, int n) {
  __shared__ int s[512];
  int tid = threadIdx.x;
  int i = blockIdx.x * 512 + tid;
  int v = (i < n) ? in[i] : 0;
  s[tid] = v;
  __syncthreads();
  for (int off = 1; off < 512; off <<= 1) {
    int t = (tid >= off) ? s[tid - off] : 0;
    __syncthreads();
    s[tid] += t;
    __syncthreads();
  }
  if (i < n) outExcl[i] = s[tid] - v;
  if (tid == 511 && bsums) bsums[blockIdx.x] = s[511];
}

__global__ void scan_add_kernel(int* __restrict__ outExcl,
                                const int* __restrict__ bscan, int n) {
  int i = blockIdx.x * 512 + threadIdx.x;
  if (i < n) outExcl[i] += bscan[blockIdx.x];
}

__global__ void scatter2_kernel(const int* __restrict__ src_dp,
                                const int* __restrict__ dst_dp,
                                const int* __restrict__ src_pd,
                                const int* __restrict__ dst_pd,
                                const int* __restrict__ off,
                                int* __restrict__ cur, int* __restrict__ ssrc) {
  int i = blockIdx.x * blockDim.x + threadIdx.x;
  if (i < 2 * EE) {
    int s, nidx;
    if (i < EE) { s = src_dp[i]; nidx = dst_dp[i]; }
    else        { s = src_pd[i - EE]; nidx = NN + dst_pd[i - EE]; }
    int p = atomicAdd(&cur[nidx], 1);
    ssrc[off[nidx] + p] = s;
  }
}

// ---------------- GAT aggregation: one warp per dst node -------------------
__global__ void gat_agg_kernel(const int* __restrict__ off,
                               const int* __restrict__ ssrc,
                               const float* __restrict__ el,
                               const float* __restrict__ er,
                               const float* __restrict__ Fsrc,
                               const float* __restrict__ bias,
                               float* __restrict__ out,
                               int nodeBase, int endCap, int n) {
  int w = (blockIdx.x * blockDim.x + threadIdx.x) >> 5;
  int lane = threadIdx.x & 31;
  if (w >= n) return;

  int idx = nodeBase + w;
  int beg = off[idx];
  int end = (idx + 1 < 2 * NN) ? off[idx + 1] : endCap;

  const float4* elv = reinterpret_cast<const float4*>(el);
  float4 erv = reinterpret_cast<const float4*>(er)[w];

  const float NEG = -1e30f;
  float m0 = NEG, m1 = NEG, m2 = NEG, m3 = NEG;
  float s0 = 0.f, s1 = 0.f, s2 = 0.f, s3 = 0.f;

  for (int i = beg + lane; i < end; i += 32) {
    int sp = ssrc[i];
    float4 v = elv[sp];
    float e0 = v.x + erv.x; e0 = (e0 > 0.f) ? e0 : 0.2f * e0;
    float e1 = v.y + erv.y; e1 = (e1 > 0.f) ? e1 : 0.2f * e1;
    float e2 = v.z + erv.z; e2 = (e2 > 0.f) ? e2 : 0.2f * e2;
    float e3 = v.w + erv.w; e3 = (e3 > 0.f) ? e3 : 0.2f * e3;
    float nm;
    nm = fmaxf(m0, e0); s0 = s0 * __expf(m0 - nm) + __expf(e0 - nm); m0 = nm;
    nm = fmaxf(m1, e1); s1 = s1 * __expf(m1 - nm) + __expf(e1 - nm); m1 = nm;
    nm = fmaxf(m2, e2); s2 = s2 * __expf(m2 - nm) + __expf(e2 - nm); m2 = nm;
    nm = fmaxf(m3, e3); s3 = s3 * __expf(m3 - nm) + __expf(e3 - nm); m3 = nm;
  }
  float M0 = m0, M1 = m1, M2 = m2, M3 = m3;
#pragma unroll
  for (int o = 16; o; o >>= 1) {
    M0 = fmaxf(M0, __shfl_xor_sync(0xffffffffu, M0, o));
    M1 = fmaxf(M1, __shfl_xor_sync(0xffffffffu, M1, o));
    M2 = fmaxf(M2, __shfl_xor_sync(0xffffffffu, M2, o));
    M3 = fmaxf(M3, __shfl_xor_sync(0xffffffffu, M3, o));
  }
  float t0 = s0 * __expf(m0 - M0);
  float t1 = s1 * __expf(m1 - M1);
  float t2 = s2 * __expf(m2 - M2);
  float t3 = s3 * __expf(m3 - M3);
#pragma unroll
  for (int o = 16; o; o >>= 1) {
    t0 += __shfl_xor_sync(0xffffffffu, t0, o);
    t1 += __shfl_xor_sync(0xffffffffu, t1, o);
    t2 += __shfl_xor_sync(0xffffffffu, t2, o);
    t3 += __shfl_xor_sync(0xffffffffu, t3, o);
  }

  int h = lane >> 3;
  float Mh = (h == 0) ? M0 : (h == 1) ? M1 : (h == 2) ? M2 : M3;
  float th = (h == 0) ? t0 : (h == 1) ? t1 : (h == 2) ? t2 : t3;
  float erh = (h == 0) ? erv.x : (h == 1) ? erv.y : (h == 2) ? erv.z : erv.w;
  float rh = 1.0f / th;

  float4 accv = make_float4(0.f, 0.f, 0.f, 0.f);
  for (int i = beg; i < end; i++) {
    int sp = ssrc[i];  // uniform across warp -> broadcast
    float4 v = elv[sp];
    float e = (h == 0) ? v.x : (h == 1) ? v.y : (h == 2) ? v.z : v.w;
    e += erh;
    e = (e > 0.f) ? e : 0.2f * e;
    float c = __expf(e - Mh) * rh;
    float4 f = reinterpret_cast<const float4*>(Fsrc + sp * 128)[lane];
    accv.x = fmaf(c, f.x, accv.x);
    accv.y = fmaf(c, f.y, accv.y);
    accv.z = fmaf(c, f.z, accv.z);
    accv.w = fmaf(c, f.w, accv.w);
  }
  float4 bv = reinterpret_cast<const float4*>(bias)[lane];
  accv.x += bv.x; accv.y += bv.y; accv.z += bv.z; accv.w += bv.w;
  reinterpret_cast<float4*>(out + w * 128)[lane] = accv;
}

// ---------------- launch ---------------------------------------------------
static inline void* sym(const void* s) {
  void* p = nullptr;
  cudaGetSymbolAddress(&p, s);
  return p;
}

extern "C" void kernel_launch(void* const* d_in, const int* in_sizes, int n_in,
                              void* d_out, int out_size) {
  const float* x_drug = (const float*)d_in[0];
  const float* x_prot = (const float*)d_in[1];
  const int* src_dp = (const int*)d_in[2];
  const int* dst_dp = (const int*)d_in[3];
  const int* src_pd = (const int*)d_in[4];
  const int* dst_pd = (const int*)d_in[5];
  const float* W_in_d = (const float*)d_in[6];
  const float* b_in_d = (const float*)d_in[7];
  const float* W_in_p = (const float*)d_in[8];
  const float* b_in_p = (const float*)d_in[9];
  const float* W_dp   = (const float*)d_in[10];
  const float* al_dp  = (const float*)d_in[11];
  const float* ar_dp  = (const float*)d_in[12];
  const float* bias_dp= (const float*)d_in[13];
  const float* W_pd   = (const float*)d_in[14];
  const float* al_pd  = (const float*)d_in[15];
  const float* ar_pd  = (const float*)d_in[16];
  const float* bias_pd= (const float*)d_in[17];
  const float* W_out_d= (const float*)d_in[18];
  const float* b_out_d= (const float*)d_in[19];
  const float* W_out_p= (const float*)d_in[20];
  const float* b_out_p= (const float*)d_in[21];
  float* out = (float*)d_out;

  float* h_d  = (float*)sym(g_h_d);
  float* h_p  = (float*)sym(g_h_p);
  float* Fd_dp= (float*)sym(g_Fd_dp);
  float* Fp_dp= (float*)sym(g_Fp_dp);
  float* Fp_pd= (float*)sym(g_Fp_pd);
  float* Fd_pd= (float*)sym(g_Fd_pd);
  float* agg_d= (float*)sym(g_agg_d);
  float* agg_p= (float*)sym(g_agg_p);
  float* el_d_dp = (float*)sym(g_el_d_dp);
  float* er_p_dp = (float*)sym(g_er_p_dp);
  float* el_p_pd = (float*)sym(g_el_p_pd);
  float* er_d_pd = (float*)sym(g_er_d_pd);
  int* deg  = (int*)sym(g_deg);
  int* cur  = (int*)sym(g_cur);
  int* off  = (int*)sym(g_off);
  int* bsum = (int*)sym(g_bsum);
  int* bscan= (int*)sym(g_bscan);
  int* ssrc = (int*)sym(g_ssrc);
  __nv_bfloat16* WimgH = (__nv_bfloat16*)sym(g_WimgH);
  __nv_bfloat16* WimgL = (__nv_bfloat16*)sym(g_WimgL);

  // opt-in to 136KB dynamic smem (idempotent)
  cudaFuncSetAttribute(mma_gemm_kernel<true>,
                       cudaFuncAttributeMaxDynamicSharedMemorySize, SM_TOTAL);
  cudaFuncSetAttribute(mma_gemm_kernel<false>,
                       cudaFuncAttributeMaxDynamicSharedMemorySize, SM_TOTAL);

  const int ZB  = (2 * NN + 255) / 256;
  const int EB2 = (2 * EE + 255) / 256;
  const int SB2 = (2 * NN + 511) / 512;     // 391 scan blocks
  const int GB  = (NN + 127) / 128;         // 782 gemm tiles
  const int WB  = (NN * 32 + 255) / 256;    // warp-per-node blocks

  // ---- W -> bf16 hi/lo transposed images (order: 0..5) ----
  convW_kernel<<<(6 * 16384 + 255) / 256, 256>>>(
      W_in_d, W_in_p, W_dp, W_pd, W_out_d, W_out_p, WimgH, WimgL);

  // ---- CSR build (both etypes, concatenated) ----
  zero2_kernel<<<ZB, 256>>>(deg, cur, 2 * NN);
  degree2_kernel<<<EB2, 256>>>(dst_dp, dst_pd, deg);
  scan_block_kernel<<<SB2, 512>>>(deg, off, bsum, 2 * NN);
  scan_block_kernel<<<1, 512>>>(bsum, bscan, nullptr, SB2);
  scan_add_kernel<<<SB2, 512>>>(off, bscan, 2 * NN);
  scatter2_kernel<<<EB2, 256>>>(src_dp, dst_dp, src_pd, dst_pd, off, cur, ssrc);

#define WH(i) (WimgH + (i) * 16384)
#define WL(i) (WimgL + (i) * 16384)

  // ---- input projections (relu) ----
  mma_gemm_kernel<true><<<GB, 256, SM_TOTAL>>>(x_drug, WH(0), WL(0), b_in_d,
                                               h_d, nullptr, nullptr, NN);
  mma_gemm_kernel<true><<<GB, 256, SM_TOTAL>>>(x_prot, WH(1), WL(1), b_in_p,
                                               h_p, nullptr, nullptr, NN);

  // ---- GAT feature projections with fused attention scores ----
  mma_gemm_kernel<false><<<GB, 256, SM_TOTAL>>>(h_d, WH(2), WL(2), nullptr,
                                                Fd_dp, al_dp, el_d_dp, NN);
  mma_gemm_kernel<false><<<GB, 256, SM_TOTAL>>>(h_p, WH(2), WL(2), nullptr,
                                                Fp_dp, ar_dp, er_p_dp, NN);
  mma_gemm_kernel<false><<<GB, 256, SM_TOTAL>>>(h_p, WH(3), WL(3), nullptr,
                                                Fp_pd, al_pd, el_p_pd, NN);
  mma_gemm_kernel<false><<<GB, 256, SM_TOTAL>>>(h_d, WH(3), WL(3), nullptr,
                                                Fd_pd, ar_pd, er_d_pd, NN);

  // ---- edge softmax + aggregation ----
  gat_agg_kernel<<<WB, 256>>>(off, ssrc, el_d_dp, er_p_dp, Fd_dp,
                              bias_dp, agg_p, 0, 2 * EE, NN);
  gat_agg_kernel<<<WB, 256>>>(off, ssrc, el_p_pd, er_d_pd, Fp_pd,
                              bias_pd, agg_d, NN, 2 * EE, NN);

  // ---- output projections, straight into d_out (drug first, then prot) ----
  mma_gemm_kernel<false><<<GB, 256, SM_TOTAL>>>(agg_d, WH(4), WL(4), b_out_d,
                                                out, nullptr, nullptr, NN);
  mma_gemm_kernel<false><<<GB, 256, SM_TOTAL>>>(agg_p, WH(5), WL(5), b_out_p,
                                                out + (size_t)NN * 128, nullptr,
                                                nullptr, NN);
}

// round 15
// speedup vs baseline: 2.0680x; 1.1822x over previous
#include <cuda_runtime.h>
#include <cuda_bf16.h>
#include <math.h>
#include <stdint.h>

#define NN 100000
#define EE 800000
#define HIDC 128

// ---------------- scratch (device globals; no allocations allowed) ----------
__device__ float g_Fd_dp[NN * HIDC];
__device__ float g_Fp_dp[NN * HIDC];
__device__ float g_Fp_pd[NN * HIDC];
__device__ float g_Fd_pd[NN * HIDC];
__device__ float g_agg_d[NN * HIDC];
__device__ float g_agg_p[NN * HIDC];

__device__ float g_el_d_dp[NN * 4];
__device__ float g_er_p_dp[NN * 4];
__device__ float g_el_p_pd[NN * 4];
__device__ float g_er_d_pd[NN * 4];

// CSR for both etypes, concatenated: [0,NN) = dp (dst=protein),
// [NN,2NN) = pd (dst=drug). Edge slots: dp -> [0,EE), pd -> [EE,2EE).
__device__ int g_deg[2 * NN];
__device__ int g_cur[2 * NN];
__device__ int g_off[2 * NN];
__device__ int g_bsum[512];
__device__ int g_bscan[512];
__device__ int g_ssrc[2 * EE];

// Transposed bf16 weight images Bt[n][k] (hi / lo split), 6 matrices 128x128.
__device__ __nv_bfloat16 g_WimgH[6 * 16384];
__device__ __nv_bfloat16 g_WimgL[6 * 16384];

// ---------------- mma.sync helpers (baseline PTX, works at compute_103) -----
__device__ __forceinline__ uint32_t smem_u32(const void* p) {
  uint32_t a;
  asm("{ .reg .u64 t; cvta.to.shared.u64 t, %1; cvt.u32.u64 %0, t; }"
      : "=r"(a) : "l"(p));
  return a;
}

__device__ __forceinline__ void ldm4(uint32_t* r, uint32_t addr) {
  asm volatile(
      "ldmatrix.sync.aligned.m8n8.x4.shared.b16 {%0,%1,%2,%3}, [%4];"
      : "=r"(r[0]), "=r"(r[1]), "=r"(r[2]), "=r"(r[3]) : "r"(addr));
}

__device__ __forceinline__ void mma_bf16(float* c, const uint32_t* a,
                                         uint32_t b0, uint32_t b1) {
  asm volatile(
      "mma.sync.aligned.m16n8k16.row.col.f32.bf16.bf16.f32 "
      "{%0,%1,%2,%3}, {%4,%5,%6,%7}, {%8,%9}, {%0,%1,%2,%3};"
      : "+f"(c[0]), "+f"(c[1]), "+f"(c[2]), "+f"(c[3])
      : "r"(a[0]), "r"(a[1]), "r"(a[2]), "r"(a[3]), "r"(b0), "r"(b1));
}

// SMEM tiles: 128 rows x 136 bf16, 272B padded stride (conflict-free for
// ldmatrix x4: row step = 68 words = 4 banks mod 32).
#define PADB 272
#define TILEB (128 * PADB)  // 34816

// ---------------- W -> transposed bf16 hi/lo images (one-time) --------------
__global__ void convW_kernel(const float* __restrict__ W0, const float* __restrict__ W1,
                             const float* __restrict__ W2, const float* __restrict__ W3,
                             const float* __restrict__ W4, const float* __restrict__ W5,
                             __nv_bfloat16* __restrict__ imgH,
                             __nv_bfloat16* __restrict__ imgL) {
  int i = blockIdx.x * 256 + threadIdx.x;
  if (i >= 6 * 16384) return;
  int w = i >> 14, idx = i & 16383;
  int n = idx >> 7, k = idx & 127;  // Bt[n][k] = W[k][n]
  const float* Wp = (w == 0) ? W0 : (w == 1) ? W1 : (w == 2) ? W2
                  : (w == 3) ? W3 : (w == 4) ? W4 : W5;
  float v = Wp[k * 128 + n];
  __nv_bfloat16 h = __float2bfloat16(v);
  imgH[w * 16384 + idx] = h;
  imgL[w * 16384 + idx] = __float2bfloat16(v - __bfloat162float(h));
}

// ---------------- shared device pieces --------------------------------------
__device__ __forceinline__ void stage_img(const __nv_bfloat16* __restrict__ img,
                                          char* dst, int tid) {
  const float4* b = reinterpret_cast<const float4*>(img);
#pragma unroll
  for (int t = 0; t < 8; t++) {
    int idx = t * 256 + tid;  // 0..2047
    int r = idx >> 4, q = idx & 15;
    *reinterpret_cast<float4*>(dst + r * PADB + q * 16) = b[idx];
  }
}

__device__ __forceinline__ void stage_splitA(const float* __restrict__ A,
                                             char* dH, char* dL, int row0,
                                             int M, int tid) {
#pragma unroll 4
  for (int t = 0; t < 16; t++) {
    int idx = t * 256 + tid;  // 0..4095
    int r = idx >> 5, c4 = idx & 31;
    int g = row0 + r;
    float4 v = (g < M) ? reinterpret_cast<const float4*>(A)[g * 32 + c4]
                       : make_float4(0.f, 0.f, 0.f, 0.f);
    __nv_bfloat162 h01 = __floats2bfloat162_rn(v.x, v.y);
    __nv_bfloat162 h23 = __floats2bfloat162_rn(v.z, v.w);
    __nv_bfloat162 l01 = __floats2bfloat162_rn(v.x - __bfloat162float(h01.x),
                                               v.y - __bfloat162float(h01.y));
    __nv_bfloat162 l23 = __floats2bfloat162_rn(v.z - __bfloat162float(h23.x),
                                               v.w - __bfloat162float(h23.y));
    char* ph = dH + r * PADB + c4 * 8;
    char* pl = dL + r * PADB + c4 * 8;
    *reinterpret_cast<__nv_bfloat162*>(ph) = h01;
    *reinterpret_cast<__nv_bfloat162*>(ph + 4) = h23;
    *reinterpret_cast<__nv_bfloat162*>(pl) = l01;
    *reinterpret_cast<__nv_bfloat162*>(pl + 4) = l23;
  }
}

// 3-pass Markidis mainloop: acc += Ah*Bh + Ah*Bl + Al*Bh
__device__ __forceinline__ void run_gemm(float acc[4][4][4], uint32_t aH,
                                         uint32_t aL, uint32_t bH, uint32_t bL) {
#pragma unroll
  for (int mt = 0; mt < 4; mt++)
#pragma unroll
    for (int nt = 0; nt < 4; nt++)
#pragma unroll
      for (int c = 0; c < 4; c++) acc[mt][nt][c] = 0.f;

#pragma unroll
  for (int k = 0; k < 8; k++) {
    const uint32_t ka = (uint32_t)k * 32;
    uint32_t a[4][4];
#pragma unroll
    for (int mt = 0; mt < 4; mt++) ldm4(a[mt], aH + mt * 16 * PADB + ka);
    uint32_t bh0[4], bh1[4], bl0[4], bl1[4];
    ldm4(bh0, bH + ka);
    ldm4(bh1, bH + 16 * PADB + ka);
    ldm4(bl0, bL + ka);
    ldm4(bl1, bL + 16 * PADB + ka);
#pragma unroll
    for (int mt = 0; mt < 4; mt++) {
      mma_bf16(acc[mt][0], a[mt], bh0[0], bh0[1]);
      mma_bf16(acc[mt][1], a[mt], bh0[2], bh0[3]);
      mma_bf16(acc[mt][2], a[mt], bh1[0], bh1[1]);
      mma_bf16(acc[mt][3], a[mt], bh1[2], bh1[3]);
      mma_bf16(acc[mt][0], a[mt], bl0[0], bl0[1]);
      mma_bf16(acc[mt][1], a[mt], bl0[2], bl0[3]);
      mma_bf16(acc[mt][2], a[mt], bl1[0], bl1[1]);
      mma_bf16(acc[mt][3], a[mt], bl1[2], bl1[3]);
    }
  }
#pragma unroll
  for (int k = 0; k < 8; k++) {
    const uint32_t ka = (uint32_t)k * 32;
    uint32_t a[4][4];
#pragma unroll
    for (int mt = 0; mt < 4; mt++) ldm4(a[mt], aL + mt * 16 * PADB + ka);
    uint32_t bh0[4], bh1[4];
    ldm4(bh0, bH + ka);
    ldm4(bh1, bH + 16 * PADB + ka);
#pragma unroll
    for (int mt = 0; mt < 4; mt++) {
      mma_bf16(acc[mt][0], a[mt], bh0[0], bh0[1]);
      mma_bf16(acc[mt][1], a[mt], bh0[2], bh0[3]);
      mma_bf16(acc[mt][2], a[mt], bh1[0], bh1[1]);
      mma_bf16(acc[mt][3], a[mt], bh1[2], bh1[3]);
    }
  }
}

// store C (+optional bias/relu) and optional fused attention score
__device__ __forceinline__ void epilogue(const float acc[4][4][4],
                                         float* __restrict__ C,
                                         const float* __restrict__ bias,
                                         bool relu,
                                         const float* __restrict__ avec,
                                         float* __restrict__ el_out, int row0,
                                         int m0, int n0, int wc, int lane,
                                         int M) {
  const int t4 = lane & 3, g4 = lane >> 2;

  if (el_out) {
    float av0[4], av1[4];
#pragma unroll
    for (int nt = 0; nt < 4; nt++) {
      av0[nt] = avec[n0 + nt * 8 + 2 * t4];
      av1[nt] = avec[n0 + nt * 8 + 2 * t4 + 1];
    }
#pragma unroll
    for (int mt = 0; mt < 4; mt++) {
      float p1 = 0.f, p2 = 0.f;
#pragma unroll
      for (int nt = 0; nt < 4; nt++) {
        p1 = fmaf(acc[mt][nt][0], av0[nt], p1);
        p1 = fmaf(acc[mt][nt][1], av1[nt], p1);
        p2 = fmaf(acc[mt][nt][2], av0[nt], p2);
        p2 = fmaf(acc[mt][nt][3], av1[nt], p2);
      }
      p1 += __shfl_xor_sync(0xffffffffu, p1, 1);
      p1 += __shfl_xor_sync(0xffffffffu, p1, 2);
      p2 += __shfl_xor_sync(0xffffffffu, p2, 1);
      p2 += __shfl_xor_sync(0xffffffffu, p2, 2);
      if (t4 == 0) {
        int r1 = row0 + m0 + mt * 16 + g4;
        if (r1 < M) el_out[r1 * 4 + wc] = p1;
        if (r1 + 8 < M) el_out[(r1 + 8) * 4 + wc] = p2;
      }
    }
  }

  float b0r[4], b1r[4];
  if (bias) {
#pragma unroll
    for (int nt = 0; nt < 4; nt++) {
      b0r[nt] = bias[n0 + nt * 8 + 2 * t4];
      b1r[nt] = bias[n0 + nt * 8 + 2 * t4 + 1];
    }
  }
#pragma unroll
  for (int mt = 0; mt < 4; mt++) {
    int r1 = row0 + m0 + mt * 16 + g4;
    int r2 = r1 + 8;
#pragma unroll
    for (int nt = 0; nt < 4; nt++) {
      int col = n0 + nt * 8 + 2 * t4;
      float2 v1 = make_float2(acc[mt][nt][0], acc[mt][nt][1]);
      float2 v2 = make_float2(acc[mt][nt][2], acc[mt][nt][3]);
      if (bias) {
        v1.x += b0r[nt]; v1.y += b1r[nt];
        v2.x += b0r[nt]; v2.y += b1r[nt];
      }
      if (relu) {
        v1.x = fmaxf(v1.x, 0.f); v1.y = fmaxf(v1.y, 0.f);
        v2.x = fmaxf(v2.x, 0.f); v2.y = fmaxf(v2.y, 0.f);
      }
      if (r1 < M) *reinterpret_cast<float2*>(&C[r1 * 128 + col]) = v1;
      if (r2 < M) *reinterpret_cast<float2*>(&C[r2 * 128 + col]) = v2;
    }
  }
}

// ---------------- fused projection kernel -----------------------------------
// per ntype: h = relu(x@W_in + b); F1 = h@W1 (+score a1->e1); F2 = h@W2
// (+score a2->e2). h lives only in smem (split bf16 hi/lo from registers).
// smem: T0/T1 = x then h (hi/lo); T2/T3 = W_in then W1; T4/T5 = W2.
#define FSM_TOTAL (6 * TILEB)  // 208896
__global__ __launch_bounds__(256, 1) void proj_fused_kernel(
    const float* __restrict__ x, const __nv_bfloat16* __restrict__ WinH,
    const __nv_bfloat16* __restrict__ WinL, const float* __restrict__ bin,
    const __nv_bfloat16* __restrict__ W1H, const __nv_bfloat16* __restrict__ W1L,
    float* __restrict__ F1, const float* __restrict__ a1, float* __restrict__ e1,
    const __nv_bfloat16* __restrict__ W2H, const __nv_bfloat16* __restrict__ W2L,
    float* __restrict__ F2, const float* __restrict__ a2, float* __restrict__ e2,
    int M) {
  extern __shared__ __align__(16) char smem[];
  const uint32_t sb = smem_u32(smem);
  const int tid = threadIdx.x, wid = tid >> 5, lane = tid & 31;
  const int row0 = blockIdx.x * 128;
  const int wr = wid >> 2, wc = wid & 3;
  const int m0 = wr * 64, n0 = wc * 32;

  char* T0 = smem;
  char* T1 = smem + TILEB;
  char* T2 = smem + 2 * TILEB;
  char* T3 = smem + 3 * TILEB;
  char* T4 = smem + 4 * TILEB;
  char* T5 = smem + 5 * TILEB;

  // phase 0: stage x (split) + W_in + W2
  stage_splitA(x, T0, T1, row0, M, tid);
  stage_img(WinH, T2, tid);
  stage_img(WinL, T3, tid);
  stage_img(W2H, T4, tid);
  stage_img(W2L, T5, tid);
  __syncthreads();

  const uint32_t aOff = (uint32_t)(m0 + (lane & 15)) * PADB + ((lane >> 4) << 4);
  const uint32_t bOff =
      (uint32_t)(n0 + (lane & 7) + ((lane >> 4) << 3)) * PADB +
      (((lane >> 3) & 1) << 4);

  float acc[4][4][4];

  // GEMM1: h = x @ W_in
  run_gemm(acc, sb + aOff, sb + TILEB + aOff, sb + 2 * TILEB + bOff,
           sb + 3 * TILEB + bOff);
  __syncthreads();  // everyone done reading T0..T3

  // write h (bias+relu, split hi/lo) into T0/T1; conflict-free pattern
  {
    const int t4 = lane & 3, g4 = lane >> 2;
    float b0r[4], b1r[4];
#pragma unroll
    for (int nt = 0; nt < 4; nt++) {
      b0r[nt] = bin[n0 + nt * 8 + 2 * t4];
      b1r[nt] = bin[n0 + nt * 8 + 2 * t4 + 1];
    }
#pragma unroll
    for (int mt = 0; mt < 4; mt++) {
      int r1 = m0 + mt * 16 + g4;
      int r2 = r1 + 8;
#pragma unroll
      for (int nt = 0; nt < 4; nt++) {
        int col = n0 + nt * 8 + 2 * t4;
        float vx = fmaxf(acc[mt][nt][0] + b0r[nt], 0.f);
        float vy = fmaxf(acc[mt][nt][1] + b1r[nt], 0.f);
        float wx = fmaxf(acc[mt][nt][2] + b0r[nt], 0.f);
        float wy = fmaxf(acc[mt][nt][3] + b1r[nt], 0.f);
        __nv_bfloat162 h1 = __floats2bfloat162_rn(vx, vy);
        __nv_bfloat162 l1 = __floats2bfloat162_rn(vx - __bfloat162float(h1.x),
                                                  vy - __bfloat162float(h1.y));
        __nv_bfloat162 h2 = __floats2bfloat162_rn(wx, wy);
        __nv_bfloat162 l2 = __floats2bfloat162_rn(wx - __bfloat162float(h2.x),
                                                  wy - __bfloat162float(h2.y));
        *reinterpret_cast<__nv_bfloat162*>(T0 + r1 * PADB + col * 2) = h1;
        *reinterpret_cast<__nv_bfloat162*>(T1 + r1 * PADB + col * 2) = l1;
        *reinterpret_cast<__nv_bfloat162*>(T0 + r2 * PADB + col * 2) = h2;
        *reinterpret_cast<__nv_bfloat162*>(T1 + r2 * PADB + col * 2) = l2;
      }
    }
  }
  // stage W1 over W_in
  stage_img(W1H, T2, tid);
  stage_img(W1L, T3, tid);
  __syncthreads();

  // GEMM2: F1 = h @ W1 (+score)
  run_gemm(acc, sb + aOff, sb + TILEB + aOff, sb + 2 * TILEB + bOff,
           sb + 3 * TILEB + bOff);
  epilogue(acc, F1, nullptr, false, a1, e1, row0, m0, n0, wc, lane, M);

  // GEMM3: F2 = h @ W2 (+score)  (T4/T5 staged since phase 0)
  run_gemm(acc, sb + aOff, sb + TILEB + aOff, sb + 4 * TILEB + bOff,
           sb + 5 * TILEB + bOff);
  epilogue(acc, F2, nullptr, false, a2, e2, row0, m0, n0, wc, lane, M);
}

// ---------------- plain GEMM kernel (output projections) --------------------
#define SM_TOTAL (4 * TILEB)  // 139264
__global__ __launch_bounds__(256, 1) void mma_gemm_kernel(
    const float* __restrict__ A, const __nv_bfloat16* __restrict__ BtH,
    const __nv_bfloat16* __restrict__ BtL, const float* __restrict__ bias,
    float* __restrict__ C, int M) {
  extern __shared__ __align__(16) char smem[];
  const uint32_t sb = smem_u32(smem);
  const int tid = threadIdx.x, wid = tid >> 5, lane = tid & 31;
  const int row0 = blockIdx.x * 128;
  const int wr = wid >> 2, wc = wid & 3;
  const int m0 = wr * 64, n0 = wc * 32;

  stage_img(BtH, smem + 2 * TILEB, tid);
  stage_img(BtL, smem + 3 * TILEB, tid);
  stage_splitA(A, smem, smem + TILEB, row0, M, tid);
  __syncthreads();

  const uint32_t aOff = (uint32_t)(m0 + (lane & 15)) * PADB + ((lane >> 4) << 4);
  const uint32_t bOff =
      (uint32_t)(n0 + (lane & 7) + ((lane >> 4) << 3)) * PADB +
      (((lane >> 3) & 1) << 4);

  float acc[4][4][4];
  run_gemm(acc, sb + aOff, sb + TILEB + aOff, sb + 2 * TILEB + bOff,
           sb + 3 * TILEB + bOff);
  epilogue(acc, C, bias, false, nullptr, nullptr, row0, m0, n0, wc, lane, M);
}

// ---------------- CSR build (both etypes in one pass) ----------------------
__global__ void zero2_kernel(int* a, int* b, int n) {
  int i = blockIdx.x * blockDim.x + threadIdx.x;
  if (i < n) { a[i] = 0; b[i] = 0; }
}

__global__ void degree2_kernel(const int* __restrict__ dst_dp,
                               const int* __restrict__ dst_pd,
                               int* __restrict__ deg) {
  int i = blockIdx.x * blockDim.x + threadIdx.x;
  if (i < 2 * EE) {
    int nidx = (i < EE) ? dst_dp[i] : (NN + dst_pd[i - EE]);
    atomicAdd(&deg[nidx], 1);
  }
}

__global__ void scan_block_kernel(const int* __restrict__ in,
                                  int* __restrict__ outExcl,
                                  int* __restrict__ bsums, int n) {
  __shared__ int s[512];
  int tid = threadIdx.x;
  int i = blockIdx.x * 512 + tid;
  int v = (i < n) ? in[i] : 0;
  s[tid] = v;
  __syncthreads();
  for (int off = 1; off < 512; off <<= 1) {
    int t = (tid >= off) ? s[tid - off] : 0;
    __syncthreads();
    s[tid] += t;
    __syncthreads();
  }
  if (i < n) outExcl[i] = s[tid] - v;
  if (tid == 511 && bsums) bsums[blockIdx.x] = s[511];
}

__global__ void scan_add_kernel(int* __restrict__ outExcl,
                                const int* __restrict__ bscan, int n) {
  int i = blockIdx.x * 512 + threadIdx.x;
  if (i < n) outExcl[i] += bscan[blockIdx.x];
}

__global__ void scatter2_kernel(const int* __restrict__ src_dp,
                                const int* __restrict__ dst_dp,
                                const int* __restrict__ src_pd,
                                const int* __restrict__ dst_pd,
                                const int* __restrict__ off,
                                int* __restrict__ cur, int* __restrict__ ssrc) {
  int i = blockIdx.x * blockDim.x + threadIdx.x;
  if (i < 2 * EE) {
    int s, nidx;
    if (i < EE) { s = src_dp[i]; nidx = dst_dp[i]; }
    else        { s = src_pd[i - EE]; nidx = NN + dst_pd[i - EE]; }
    int p = atomicAdd(&cur[nidx], 1);
    ssrc[off[nidx] + p] = s;
  }
}

// ---------------- GAT aggregation: one warp per dst node -------------------
__global__ void gat_agg_kernel(const int* __restrict__ off,
                               const int* __restrict__ ssrc,
                               const float* __restrict__ el,
                               const float* __restrict__ er,
                               const float* __restrict__ Fsrc,
                               const float* __restrict__ bias,
                               float* __restrict__ out,
                               int nodeBase, int endCap, int n) {
  int w = (blockIdx.x * blockDim.x + threadIdx.x) >> 5;
  int lane = threadIdx.x & 31;
  if (w >= n) return;

  int idx = nodeBase + w;
  int beg = off[idx];
  int end = (idx + 1 < 2 * NN) ? off[idx + 1] : endCap;

  const float4* elv = reinterpret_cast<const float4*>(el);
  float4 erv = reinterpret_cast<const float4*>(er)[w];

  const float NEG = -1e30f;
  float m0 = NEG, m1 = NEG, m2 = NEG, m3 = NEG;
  float s0 = 0.f, s1 = 0.f, s2 = 0.f, s3 = 0.f;

  for (int i = beg + lane; i < end; i += 32) {
    int sp = ssrc[i];
    float4 v = elv[sp];
    float e0 = v.x + erv.x; e0 = (e0 > 0.f) ? e0 : 0.2f * e0;
    float e1 = v.y + erv.y; e1 = (e1 > 0.f) ? e1 : 0.2f * e1;
    float e2 = v.z + erv.z; e2 = (e2 > 0.f) ? e2 : 0.2f * e2;
    float e3 = v.w + erv.w; e3 = (e3 > 0.f) ? e3 : 0.2f * e3;
    float nm;
    nm = fmaxf(m0, e0); s0 = s0 * __expf(m0 - nm) + __expf(e0 - nm); m0 = nm;
    nm = fmaxf(m1, e1); s1 = s1 * __expf(m1 - nm) + __expf(e1 - nm); m1 = nm;
    nm = fmaxf(m2, e2); s2 = s2 * __expf(m2 - nm) + __expf(e2 - nm); m2 = nm;
    nm = fmaxf(m3, e3); s3 = s3 * __expf(m3 - nm) + __expf(e3 - nm); m3 = nm;
  }
  float M0 = m0, M1 = m1, M2 = m2, M3 = m3;
#pragma unroll
  for (int o = 16; o; o >>= 1) {
    M0 = fmaxf(M0, __shfl_xor_sync(0xffffffffu, M0, o));
    M1 = fmaxf(M1, __shfl_xor_sync(0xffffffffu, M1, o));
    M2 = fmaxf(M2, __shfl_xor_sync(0xffffffffu, M2, o));
    M3 = fmaxf(M3, __shfl_xor_sync(0xffffffffu, M3, o));
  }
  float t0 = s0 * __expf(m0 - M0);
  float t1 = s1 * __expf(m1 - M1);
  float t2 = s2 * __expf(m2 - M2);
  float t3 = s3 * __expf(m3 - M3);
#pragma unroll
  for (int o = 16; o; o >>= 1) {
    t0 += __shfl_xor_sync(0xffffffffu, t0, o);
    t1 += __shfl_xor_sync(0xffffffffu, t1, o);
    t2 += __shfl_xor_sync(0xffffffffu, t2, o);
    t3 += __shfl_xor_sync(0xffffffffu, t3, o);
  }

  int h = lane >> 3;
  float Mh = (h == 0) ? M0 : (h == 1) ? M1 : (h == 2) ? M2 : M3;
  float th = (h == 0) ? t0 : (h == 1) ? t1 : (h == 2) ? t2 : t3;
  float erh = (h == 0) ? erv.x : (h == 1) ? erv.y : (h == 2) ? erv.z : erv.w;
  float rh = 1.0f / th;

  float4 accv = make_float4(0.f, 0.f, 0.f, 0.f);
  for (int i = beg; i < end; i++) {
    int sp = ssrc[i];  // uniform across warp -> broadcast
    float4 v = elv[sp];
    float e = (h == 0) ? v.x : (h == 1) ? v.y : (h == 2) ? v.z : v.w;
    e += erh;
    e = (e > 0.f) ? e : 0.2f * e;
    float c = __expf(e - Mh) * rh;
    float4 f = reinterpret_cast<const float4*>(Fsrc + sp * 128)[lane];
    accv.x = fmaf(c, f.x, accv.x);
    accv.y = fmaf(c, f.y, accv.y);
    accv.z = fmaf(c, f.z, accv.z);
    accv.w = fmaf(c, f.w, accv.w);
  }
  float4 bv = reinterpret_cast<const float4*>(bias)[lane];
  accv.x += bv.x; accv.y += bv.y; accv.z += bv.z; accv.w += bv.w;
  reinterpret_cast<float4*>(out + w * 128)[lane] = accv;
}

// ---------------- launch ---------------------------------------------------
static inline void* sym(const void* s) {
  void* p = nullptr;
  cudaGetSymbolAddress(&p, s);
  return p;
}

extern "C" void kernel_launch(void* const* d_in, const int* in_sizes, int n_in,
                              void* d_out, int out_size) {
  const float* x_drug = (const float*)d_in[0];
  const float* x_prot = (const float*)d_in[1];
  const int* src_dp = (const int*)d_in[2];
  const int* dst_dp = (const int*)d_in[3];
  const int* src_pd = (const int*)d_in[4];
  const int* dst_pd = (const int*)d_in[5];
  const float* b_in_d = (const float*)d_in[7];
  const float* b_in_p = (const float*)d_in[9];
  const float* al_dp  = (const float*)d_in[11];
  const float* ar_dp  = (const float*)d_in[12];
  const float* bias_dp= (const float*)d_in[13];
  const float* al_pd  = (const float*)d_in[15];
  const float* ar_pd  = (const float*)d_in[16];
  const float* bias_pd= (const float*)d_in[17];
  const float* b_out_d= (const float*)d_in[19];
  const float* b_out_p= (const float*)d_in[21];
  const float* W_in_d = (const float*)d_in[6];
  const float* W_in_p = (const float*)d_in[8];
  const float* W_dp   = (const float*)d_in[10];
  const float* W_pd   = (const float*)d_in[14];
  const float* W_out_d= (const float*)d_in[18];
  const float* W_out_p= (const float*)d_in[20];
  float* out = (float*)d_out;

  float* Fd_dp= (float*)sym(g_Fd_dp);
  float* Fp_dp= (float*)sym(g_Fp_dp);
  float* Fp_pd= (float*)sym(g_Fp_pd);
  float* Fd_pd= (float*)sym(g_Fd_pd);
  float* agg_d= (float*)sym(g_agg_d);
  float* agg_p= (float*)sym(g_agg_p);
  float* el_d_dp = (float*)sym(g_el_d_dp);
  float* er_p_dp = (float*)sym(g_er_p_dp);
  float* el_p_pd = (float*)sym(g_el_p_pd);
  float* er_d_pd = (float*)sym(g_er_d_pd);
  int* deg  = (int*)sym(g_deg);
  int* cur  = (int*)sym(g_cur);
  int* off  = (int*)sym(g_off);
  int* bsum = (int*)sym(g_bsum);
  int* bscan= (int*)sym(g_bscan);
  int* ssrc = (int*)sym(g_ssrc);
  __nv_bfloat16* WimgH = (__nv_bfloat16*)sym(g_WimgH);
  __nv_bfloat16* WimgL = (__nv_bfloat16*)sym(g_WimgL);

  cudaFuncSetAttribute(proj_fused_kernel,
                       cudaFuncAttributeMaxDynamicSharedMemorySize, FSM_TOTAL);
  cudaFuncSetAttribute(mma_gemm_kernel,
                       cudaFuncAttributeMaxDynamicSharedMemorySize, SM_TOTAL);

  const int ZB  = (2 * NN + 255) / 256;
  const int EB2 = (2 * EE + 255) / 256;
  const int SB2 = (2 * NN + 511) / 512;     // 391 scan blocks
  const int GB  = (NN + 127) / 128;         // 782 gemm tiles
  const int WB  = (NN * 32 + 255) / 256;    // warp-per-node blocks

  // ---- W -> bf16 hi/lo transposed images (order: 0..5) ----
  convW_kernel<<<(6 * 16384 + 255) / 256, 256>>>(
      W_in_d, W_in_p, W_dp, W_pd, W_out_d, W_out_p, WimgH, WimgL);

  // ---- CSR build (both etypes, concatenated) ----
  zero2_kernel<<<ZB, 256>>>(deg, cur, 2 * NN);
  degree2_kernel<<<EB2, 256>>>(dst_dp, dst_pd, deg);
  scan_block_kernel<<<SB2, 512>>>(deg, off, bsum, 2 * NN);
  scan_block_kernel<<<1, 512>>>(bsum, bscan, nullptr, SB2);
  scan_add_kernel<<<SB2, 512>>>(off, bscan, 2 * NN);
  scatter2_kernel<<<EB2, 256>>>(src_dp, dst_dp, src_pd, dst_pd, off, cur, ssrc);

#define WH(i) (WimgH + (i) * 16384)
#define WL(i) (WimgL + (i) * 16384)

  // ---- fused projections: x -> h (smem only) -> {F_dp, F_pd} + scores ----
  // drug: h_d@W_dp -> Fd_dp (el_d_dp via al_dp); h_d@W_pd -> Fd_pd (er_d_pd via ar_pd)
  proj_fused_kernel<<<GB, 256, FSM_TOTAL>>>(
      x_drug, WH(0), WL(0), b_in_d,
      WH(2), WL(2), Fd_dp, al_dp, el_d_dp,
      WH(3), WL(3), Fd_pd, ar_pd, er_d_pd, NN);
  // prot: h_p@W_dp -> Fp_dp (er_p_dp via ar_dp); h_p@W_pd -> Fp_pd (el_p_pd via al_pd)
  proj_fused_kernel<<<GB, 256, FSM_TOTAL>>>(
      x_prot, WH(1), WL(1), b_in_p,
      WH(2), WL(2), Fp_dp, ar_dp, er_p_dp,
      WH(3), WL(3), Fp_pd, al_pd, el_p_pd, NN);

  // ---- edge softmax + aggregation ----
  gat_agg_kernel<<<WB, 256>>>(off, ssrc, el_d_dp, er_p_dp, Fd_dp,
                              bias_dp, agg_p, 0, 2 * EE, NN);
  gat_agg_kernel<<<WB, 256>>>(off, ssrc, el_p_pd, er_d_pd, Fp_pd,
                              bias_pd, agg_d, NN, 2 * EE, NN);

  // ---- output projections, straight into d_out (drug first, then prot) ----
  mma_gemm_kernel<<<GB, 256, SM_TOTAL>>>(agg_d, WH(4), WL(4), b_out_d, out, NN);
  mma_gemm_kernel<<<GB, 256, SM_TOTAL>>>(agg_p, WH(5), WL(5), b_out_p,
                                         out + (size_t)NN * 128, NN);
}